// round 2
// baseline (speedup 1.0000x reference)
#include <cuda_runtime.h>

#define NATOM 30000
#define NNJ 12
#define KD 32
#define FD 128
#define LDA 132

// ---------------- device scratch (no allocations allowed) ----------------
__device__ float g_sfea[NATOM * FD];
__device__ float g_pfea[NATOM * FD];
__device__ float g_dfea[NATOM * FD];
__device__ float g_allp[NATOM * 3 * FD];   // [n][a][f]
__device__ float g_alld[NATOM * 5 * FD];   // [n][a][f]
__device__ float g_Mp[FD * FD];            // P1 @ P2^T
__device__ float g_Md[FD * FD];            // D1 @ D2^T
__device__ float g_rowp[NATOM * 3];
__device__ float g_rowd[NATOM * 5];

__device__ __forceinline__ float siluf(float x) {
    return x / (1.0f + __expf(-x));
}

// ---------------- K1: Mp = P1 @ P2^T, Md = D1 @ D2^T ----------------
// grid (16, 2), 128 threads. Block computes 8 rows x 128 cols.
__global__ __launch_bounds__(128)
void k_mmt(const float* __restrict__ P1, const float* __restrict__ P2,
           const float* __restrict__ D1, const float* __restrict__ D2)
{
    const float* A = blockIdx.y ? D1 : P1;
    const float* B = blockIdx.y ? D2 : P2;
    float* M = blockIdx.y ? g_Md : g_Mp;

    __shared__ float smA[8 * FD];
    __shared__ float smB[16 * LDA];
    int t = threadIdx.x;
    int i0 = blockIdx.x * 8;

    // stage 8 A rows (1024 floats = 256 float4)
#pragma unroll
    for (int r = 0; r < 2; r++) {
        int e = t + r * 128;
        ((float4*)smA)[e] = ((const float4*)A)[i0 * 32 + e];
    }

    float acc[8];
#pragma unroll
    for (int i = 0; i < 8; i++) acc[i] = 0.f;

    for (int g0 = 0; g0 < FD; g0 += 16) {
        __syncthreads();
        // stage B^T slice: smB[gl][j] = B[j][g0+gl]
#pragma unroll
        for (int r = 0; r < 4; r++) {
            int e = t + r * 128;          // 0..511
            int j = e >> 2, q = e & 3;
            float4 v = ((const float4*)B)[j * 32 + (g0 >> 2) + q];
            smB[(q * 4 + 0) * LDA + j] = v.x;
            smB[(q * 4 + 1) * LDA + j] = v.y;
            smB[(q * 4 + 2) * LDA + j] = v.z;
            smB[(q * 4 + 3) * LDA + j] = v.w;
        }
        __syncthreads();
#pragma unroll
        for (int gl = 0; gl < 16; gl++) {
            float b = smB[gl * LDA + t];
#pragma unroll
            for (int i = 0; i < 8; i++)
                acc[i] = fmaf(smA[i * FD + g0 + gl], b, acc[i]);
        }
    }
#pragma unroll
    for (int i = 0; i < 8; i++) M[(i0 + i) * FD + t] = acc[i];
}

// ---------------- K2: fused ResMLP ----------------
// out = silu(h) @ w1^T + b1,  h = x + silu(x) @ wr^T + br
// Block: 64 rows x 128 cols, 256 threads (16x16), 4x8 per thread.
struct MlpArgs {
    const float* wr[4]; const float* br[4];
    const float* w1[4]; const float* b1[4];
};

// One reduction pass: acc[i][j] = sum_g smA[m][g] * W[fout][g]
__device__ __forceinline__ void gemm_pass(const float* __restrict__ W,
                                          float acc[4][8],
                                          float* smA, float* smW,
                                          int t, int mb, int gb)
{
#pragma unroll
    for (int i = 0; i < 4; i++)
#pragma unroll
        for (int j = 0; j < 8; j++) acc[i][j] = 0.f;

    for (int g0 = 0; g0 < FD; g0 += 16) {
        __syncthreads();
        // stage transpose: smW[gl][fout] = W[fout][g0+gl]
#pragma unroll
        for (int r = 0; r < 2; r++) {
            int e = t + r * 256;          // 0..511
            int fout = e >> 2, q = e & 3;
            float4 v = ((const float4*)W)[fout * 32 + (g0 >> 2) + q];
            smW[(q * 4 + 0) * LDA + fout] = v.x;
            smW[(q * 4 + 1) * LDA + fout] = v.y;
            smW[(q * 4 + 2) * LDA + fout] = v.z;
            smW[(q * 4 + 3) * LDA + fout] = v.w;
        }
        __syncthreads();
#pragma unroll
        for (int gl = 0; gl < 16; gl++) {
            float4 b0 = *(float4*)&smW[gl * LDA + gb];
            float4 b1 = *(float4*)&smW[gl * LDA + gb + 4];
            float bv[8] = {b0.x, b0.y, b0.z, b0.w, b1.x, b1.y, b1.z, b1.w};
            float av[4];
#pragma unroll
            for (int i = 0; i < 4; i++) av[i] = smA[(mb + i) * LDA + g0 + gl];
#pragma unroll
            for (int i = 0; i < 4; i++)
#pragma unroll
                for (int j = 0; j < 8; j++)
                    acc[i][j] = fmaf(av[i], bv[j], acc[i][j]);
        }
    }
    __syncthreads();   // protect smA against the epilogue's overwrites
}

__global__ __launch_bounds__(256)
void k_resmlp(const float* __restrict__ x, MlpArgs args, float* __restrict__ out)
{
    __shared__ float smA[64 * LDA];
    __shared__ float smW[16 * LDA];

    int ch = blockIdx.y;
    const float* wr = args.wr[ch];
    const float* brp = args.br[ch];
    const float* w1 = args.w1[ch];
    const float* b1p = args.b1[ch];
    float* dst = (ch == 0) ? out : (ch == 1) ? g_sfea : (ch == 2) ? g_pfea : g_dfea;

    int row0 = blockIdx.x * 64;
    int t = threadIdx.x;
    int tx = t & 15, ty = t >> 4;
    int mb = ty * 4, gb = tx * 8;

    // stage silu(x): 64x128 floats = 2048 float4
#pragma unroll
    for (int r = 0; r < 8; r++) {
        int e = t + r * 256;
        int m = e >> 5, c4 = e & 31;
        int gr = row0 + m;
        float4 v = make_float4(0.f, 0.f, 0.f, 0.f);
        if (gr < NATOM) v = ((const float4*)x)[gr * 32 + c4];
        float4 s = make_float4(siluf(v.x), siluf(v.y), siluf(v.z), siluf(v.w));
        *(float4*)&smA[m * LDA + c4 * 4] = s;
    }

    float acc[4][8];

    // GEMM 1: silu(x) @ wr^T
    gemm_pass(wr, acc, smA, smW, t, mb, gb);

    // epilogue 1: h = acc + x + br ; smA = silu(h)
#pragma unroll
    for (int i = 0; i < 4; i++) {
        int gr = row0 + mb + i;
        float4 x0 = make_float4(0.f, 0.f, 0.f, 0.f), x1 = x0;
        if (gr < NATOM) {
            x0 = ((const float4*)x)[gr * 32 + (gb >> 2)];
            x1 = ((const float4*)x)[gr * 32 + (gb >> 2) + 1];
        }
        float xv[8] = {x0.x, x0.y, x0.z, x0.w, x1.x, x1.y, x1.z, x1.w};
#pragma unroll
        for (int j = 0; j < 8; j++) {
            float h = acc[i][j] + xv[j] + brp[gb + j];
            smA[(mb + i) * LDA + gb + j] = siluf(h);
        }
    }

    // GEMM 2: silu(h) @ w1^T   (gemm_pass's first sync orders epilogue writes)
    gemm_pass(w1, acc, smA, smW, t, mb, gb);

    // epilogue 2: write out + b1
#pragma unroll
    for (int i = 0; i < 4; i++) {
        int gr = row0 + mb + i;
        if (gr < NATOM) {
            float4 o0 = make_float4(acc[i][0] + b1p[gb + 0], acc[i][1] + b1p[gb + 1],
                                    acc[i][2] + b1p[gb + 2], acc[i][3] + b1p[gb + 3]);
            float4 o1 = make_float4(acc[i][4] + b1p[gb + 4], acc[i][5] + b1p[gb + 5],
                                    acc[i][6] + b1p[gb + 6], acc[i][7] + b1p[gb + 7]);
            ((float4*)dst)[gr * 32 + (gb >> 2)] = o0;
            ((float4*)dst)[gr * 32 + (gb >> 2) + 1] = o1;
        }
    }
}

// ---------------- K3: env contraction + neighbor gather/reduce ----------------
// one block = one atom, thread = feature f
__global__ __launch_bounds__(128)
void k_env(const int* __restrict__ nbr,
           const float* __restrict__ gs, const float* __restrict__ gp,
           const float* __restrict__ gd,
           const float* __restrict__ Gs, const float* __restrict__ Gp,
           const float* __restrict__ Gd,
           float* __restrict__ out)
{
    __shared__ float sms[NNJ * KD];        // [j][k]
    __shared__ float smp[NNJ * 3 * 36];    // [(j,a)][k] padded to 36
    __shared__ float smd[NNJ * 5 * 36];
    __shared__ int snbr[NNJ];

    int n = blockIdx.x;
    int f = threadIdx.x;
    if (f < NNJ) snbr[f] = nbr[n * NNJ + f];

    {   // stage gs (k already innermost)
        const float4* src = (const float4*)(gs + (size_t)n * NNJ * KD);
        for (int e = f; e < NNJ * KD / 4; e += 128)
            ((float4*)sms)[e] = src[e];
    }
    {   // stage gp with (k,a)->(a,k) transpose
        const float4* src = (const float4*)(gp + (size_t)n * NNJ * KD * 3);
        for (int e = f; e < NNJ * KD * 3 / 4; e += 128) {
            float4 v = src[e];
            int i0 = e * 4;
#pragma unroll
            for (int u = 0; u < 4; u++) {
                int idx = i0 + u;
                int j = idx / 96, rr = idx % 96, k = rr / 3, a = rr % 3;
                smp[(j * 3 + a) * 36 + k] = ((const float*)&v)[u];
            }
        }
    }
    {   // stage gd with transpose
        const float4* src = (const float4*)(gd + (size_t)n * NNJ * KD * 5);
        for (int e = f; e < NNJ * KD * 5 / 4; e += 128) {
            float4 v = src[e];
            int i0 = e * 4;
#pragma unroll
            for (int u = 0; u < 4; u++) {
                int idx = i0 + u;
                int j = idx / 160, rr = idx % 160, k = rr / 5, a = rr % 5;
                smd[(j * 5 + a) * 36 + k] = ((const float*)&v)[u];
            }
        }
    }
    __syncthreads();

    // ---- s channel: out += sum_j s_fea[nbr_j] * (Gs_f . gs_j) ----
    {
        float G[KD];
        const float4* gr4 = (const float4*)(Gs + f * KD);
#pragma unroll
        for (int q = 0; q < 8; q++) {
            float4 v = gr4[q];
            G[q*4] = v.x; G[q*4+1] = v.y; G[q*4+2] = v.z; G[q*4+3] = v.w;
        }
        float acc = 0.f;
#pragma unroll 2
        for (int j = 0; j < NNJ; j++) {
            float fea = g_sfea[(size_t)snbr[j] * FD + f];
            float e0 = 0.f, e1 = 0.f, e2 = 0.f, e3 = 0.f;
#pragma unroll
            for (int q = 0; q < 8; q++) {
                float4 v = *(const float4*)&sms[j * KD + q * 4];
                e0 = fmaf(G[q*4],   v.x, e0);
                e1 = fmaf(G[q*4+1], v.y, e1);
                e2 = fmaf(G[q*4+2], v.z, e2);
                e3 = fmaf(G[q*4+3], v.w, e3);
            }
            acc = fmaf(fea, (e0 + e1) + (e2 + e3), acc);
        }
        out[(size_t)n * FD + f] += acc;
    }

    // ---- p channel: all_p[n][a][f] ----
    {
        float G[KD];
        const float4* gr4 = (const float4*)(Gp + f * KD);
#pragma unroll
        for (int q = 0; q < 8; q++) {
            float4 v = gr4[q];
            G[q*4] = v.x; G[q*4+1] = v.y; G[q*4+2] = v.z; G[q*4+3] = v.w;
        }
        float acc[3] = {0.f, 0.f, 0.f};
#pragma unroll 2
        for (int j = 0; j < NNJ; j++) {
            float fea = g_pfea[(size_t)snbr[j] * FD + f];
#pragma unroll
            for (int a = 0; a < 3; a++) {
                const float* b = &smp[(j * 3 + a) * 36];
                float env = 0.f;
#pragma unroll
                for (int q = 0; q < 8; q++) {
                    float4 v = *(const float4*)(b + q * 4);
                    env = fmaf(G[q*4], v.x,
                          fmaf(G[q*4+1], v.y,
                          fmaf(G[q*4+2], v.z,
                          fmaf(G[q*4+3], v.w, env))));
                }
                acc[a] = fmaf(fea, env, acc[a]);
            }
        }
#pragma unroll
        for (int a = 0; a < 3; a++)
            g_allp[((size_t)n * 3 + a) * FD + f] = acc[a];
    }

    // ---- d channel: all_d[n][a][f] ----
    {
        float G[KD];
        const float4* gr4 = (const float4*)(Gd + f * KD);
#pragma unroll
        for (int q = 0; q < 8; q++) {
            float4 v = gr4[q];
            G[q*4] = v.x; G[q*4+1] = v.y; G[q*4+2] = v.z; G[q*4+3] = v.w;
        }
        float acc[5] = {0.f, 0.f, 0.f, 0.f, 0.f};
#pragma unroll 2
        for (int j = 0; j < NNJ; j++) {
            float fea = g_dfea[(size_t)snbr[j] * FD + f];
#pragma unroll
            for (int a = 0; a < 5; a++) {
                const float* b = &smd[(j * 5 + a) * 36];
                float env = 0.f;
#pragma unroll
                for (int q = 0; q < 8; q++) {
                    float4 v = *(const float4*)(b + q * 4);
                    env = fmaf(G[q*4], v.x,
                          fmaf(G[q*4+1], v.y,
                          fmaf(G[q*4+2], v.z,
                          fmaf(G[q*4+3], v.w, env))));
                }
                acc[a] = fmaf(fea, env, acc[a]);
            }
        }
#pragma unroll
        for (int a = 0; a < 5; a++)
            g_alld[((size_t)n * 5 + a) * FD + f] = acc[a];
    }
}

// ---------------- K4: rowdot[r] = v_r . (M v_r) ----------------
// which==0: V=g_allp, M=g_Mp, R=3N, rowdot=g_rowp ; which==1: d-channel.
__global__ __launch_bounds__(256)
void k_quad(int which)
{
    const float* V = which ? g_alld : g_allp;
    const float* M = which ? g_Md : g_Mp;
    float* rowdot = which ? g_rowd : g_rowp;
    int R = which ? NATOM * 5 : NATOM * 3;

    __shared__ float smA[64 * LDA];
    __shared__ float smW[16 * LDA];

    int row0 = blockIdx.x * 64;
    int t = threadIdx.x;
    int tx = t & 15, ty = t >> 4;
    int mb = ty * 4, gb = tx * 8;

    // stage V tile
#pragma unroll
    for (int r = 0; r < 8; r++) {
        int e = t + r * 256;
        int m = e >> 5, c4 = e & 31;
        int gr = row0 + m;
        float4 v = make_float4(0.f, 0.f, 0.f, 0.f);
        if (gr < R) v = ((const float4*)V)[gr * 32 + c4];
        *(float4*)&smA[m * LDA + c4 * 4] = v;
    }

    float acc[4][8];
#pragma unroll
    for (int i = 0; i < 4; i++)
#pragma unroll
        for (int j = 0; j < 8; j++) acc[i][j] = 0.f;

    for (int f0 = 0; f0 < FD; f0 += 16) {
        __syncthreads();
        // stage M slice directly: smW[fl][g] = M[f0+fl][g]
#pragma unroll
        for (int r = 0; r < 2; r++) {
            int e = t + r * 256;          // 0..511
            int fl = e >> 5, q = e & 31;
            float4 v = ((const float4*)M)[(f0 + fl) * 32 + q];
            *(float4*)&smW[fl * LDA + q * 4] = v;
        }
        __syncthreads();
#pragma unroll
        for (int fl = 0; fl < 16; fl++) {
            float4 b0 = *(float4*)&smW[fl * LDA + gb];
            float4 b1 = *(float4*)&smW[fl * LDA + gb + 4];
            float bv[8] = {b0.x, b0.y, b0.z, b0.w, b1.x, b1.y, b1.z, b1.w};
            float av[4];
#pragma unroll
            for (int i = 0; i < 4; i++) av[i] = smA[(mb + i) * LDA + f0 + fl];
#pragma unroll
            for (int i = 0; i < 4; i++)
#pragma unroll
                for (int j = 0; j < 8; j++)
                    acc[i][j] = fmaf(av[i], bv[j], acc[i][j]);
        }
    }

    // fused row dot: rowdot[r] = sum_g C[r][g] * V[r][g]
#pragma unroll
    for (int i = 0; i < 4; i++) {
        float d = 0.f;
#pragma unroll
        for (int j = 0; j < 8; j++)
            d = fmaf(acc[i][j], smA[(mb + i) * LDA + gb + j], d);
#pragma unroll
        for (int o = 8; o > 0; o >>= 1)
            d += __shfl_down_sync(0xffffffffu, d, o, 16);
        int gr = row0 + mb + i;
        if (tx == 0 && gr < R) rowdot[gr] = d;
    }
}

// ---------------- K5: broadcast scalar add ----------------
__global__ void k_final(float* __restrict__ out)
{
    int idx = blockIdx.x * blockDim.x + threadIdx.x;
    if (idx >= NATOM * FD) return;
    int n = idx >> 7;
    float s = g_rowp[n * 3 + 0] + g_rowp[n * 3 + 1] + g_rowp[n * 3 + 2]
            + g_rowd[n * 5 + 0] + g_rowd[n * 5 + 1] + g_rowd[n * 5 + 2]
            + g_rowd[n * 5 + 3] + g_rowd[n * 5 + 4];
    out[idx] += s;
}

// ---------------- launch ----------------
extern "C" void kernel_launch(void* const* d_in, const int* in_sizes, int n_in,
                              void* d_out, int out_size)
{
    const float* atom = (const float*)d_in[0];
    const int*   nbr  = (const int*)d_in[1];
    const float* gs   = (const float*)d_in[2];
    const float* gp   = (const float*)d_in[3];
    const float* gd   = (const float*)d_in[4];
    const float* Gs   = (const float*)d_in[5];
    const float* Gp   = (const float*)d_in[6];
    const float* Gd   = (const float*)d_in[7];
    const float* P1   = (const float*)d_in[8];
    const float* P2   = (const float*)d_in[9];
    const float* D1   = (const float*)d_in[10];
    const float* D2   = (const float*)d_in[11];
    float* out = (float*)d_out;

    MlpArgs a;
    // channel order: c(->out), s, p, d  — inputs 12..27 in order c,s,p,d
    for (int ch = 0; ch < 4; ch++) {
        a.wr[ch] = (const float*)d_in[12 + ch * 4 + 0];
        a.br[ch] = (const float*)d_in[12 + ch * 4 + 1];
        a.w1[ch] = (const float*)d_in[12 + ch * 4 + 2];
        a.b1[ch] = (const float*)d_in[12 + ch * 4 + 3];
    }

    k_mmt<<<dim3(16, 2), 128>>>(P1, P2, D1, D2);
    k_resmlp<<<dim3((NATOM + 63) / 64, 4), 256>>>(atom, a, out);
    k_env<<<NATOM, 128>>>(nbr, gs, gp, gd, Gs, Gp, Gd, out);
    k_quad<<<(NATOM * 3 + 63) / 64, 256>>>(0);
    k_quad<<<(NATOM * 5 + 63) / 64, 256>>>(1);
    k_final<<<(NATOM * FD + 255) / 256, 256>>>(out);
}

// round 5
// speedup vs baseline: 1.4850x; 1.4850x over previous
#include <cuda_runtime.h>

#define NATOM 30000
#define NNJ 12
#define KD 32
#define FD 128
#define LDA 132

// sB layout: [32 k][152 cols]; cols: s [0,16), p a*16+[16,64), d a*16+[64,144), pads zeroed
#define LDB 152
#define SB_FLOATS (32 * LDB)           // 4864
#define FEA_LD 17
#define SFEA_FLOATS (3 * 128 * FEA_LD) // 6528

// ---------------- device scratch ----------------
__device__ float g_sfea[NATOM * FD];
__device__ float g_pfea[NATOM * FD];
__device__ float g_dfea[NATOM * FD];
__device__ float g_allp[NATOM * 3 * FD];   // [n][a][f]
__device__ float g_alld[NATOM * 5 * FD];   // [n][a][f]
__device__ float g_Mp[FD * FD];            // P1 @ P2^T
__device__ float g_Md[FD * FD];            // D1 @ D2^T
__device__ float g_rowp[NATOM * 3];
__device__ float g_rowd[NATOM * 5];

__device__ __forceinline__ float siluf(float x) {
    return x / (1.0f + __expf(-x));
}

__device__ __forceinline__ unsigned tf32r(float x) {
    unsigned u;
    asm("cvt.rna.tf32.f32 %0, %1;" : "=r"(u) : "f"(x));
    return u;
}

__device__ __forceinline__ void mma_tf32(float c[4], const unsigned a[4],
                                         unsigned b0, unsigned b1) {
    asm volatile(
        "mma.sync.aligned.m16n8k8.row.col.f32.tf32.tf32.f32 "
        "{%0,%1,%2,%3},{%4,%5,%6,%7},{%8,%9},{%0,%1,%2,%3};"
        : "+f"(c[0]), "+f"(c[1]), "+f"(c[2]), "+f"(c[3])
        : "r"(a[0]), "r"(a[1]), "r"(a[2]), "r"(a[3]), "r"(b0), "r"(b1));
}

// ---------------- K1: Mp = P1 @ P2^T, Md = D1 @ D2^T ----------------
__global__ __launch_bounds__(128)
void k_mmt(const float* __restrict__ P1, const float* __restrict__ P2,
           const float* __restrict__ D1, const float* __restrict__ D2)
{
    const float* A = blockIdx.y ? D1 : P1;
    const float* B = blockIdx.y ? D2 : P2;
    float* M = blockIdx.y ? g_Md : g_Mp;

    __shared__ float smA[8 * FD];
    __shared__ float smB[16 * LDA];
    int t = threadIdx.x;
    int i0 = blockIdx.x * 8;

#pragma unroll
    for (int r = 0; r < 2; r++) {
        int e = t + r * 128;
        ((float4*)smA)[e] = ((const float4*)A)[i0 * 32 + e];
    }

    float acc[8];
#pragma unroll
    for (int i = 0; i < 8; i++) acc[i] = 0.f;

    for (int g0 = 0; g0 < FD; g0 += 16) {
        __syncthreads();
#pragma unroll
        for (int r = 0; r < 4; r++) {
            int e = t + r * 128;
            int j = e >> 2, q = e & 3;
            float4 v = ((const float4*)B)[j * 32 + (g0 >> 2) + q];
            smB[(q * 4 + 0) * LDA + j] = v.x;
            smB[(q * 4 + 1) * LDA + j] = v.y;
            smB[(q * 4 + 2) * LDA + j] = v.z;
            smB[(q * 4 + 3) * LDA + j] = v.w;
        }
        __syncthreads();
#pragma unroll
        for (int gl = 0; gl < 16; gl++) {
            float b = smB[gl * LDA + t];
#pragma unroll
            for (int i = 0; i < 8; i++)
                acc[i] = fmaf(smA[i * FD + g0 + gl], b, acc[i]);
        }
    }
#pragma unroll
    for (int i = 0; i < 8; i++) M[(i0 + i) * FD + t] = acc[i];
}

// ---------------- K2: fused ResMLP (fp32) ----------------
struct MlpArgs {
    const float* wr[4]; const float* br[4];
    const float* w1[4]; const float* b1[4];
};

__device__ __forceinline__ void gemm_pass(const float* __restrict__ W,
                                          float acc[4][8],
                                          float* smA, float* smW,
                                          int t, int mb, int gb)
{
#pragma unroll
    for (int i = 0; i < 4; i++)
#pragma unroll
        for (int j = 0; j < 8; j++) acc[i][j] = 0.f;

    for (int g0 = 0; g0 < FD; g0 += 16) {
        __syncthreads();
#pragma unroll
        for (int r = 0; r < 2; r++) {
            int e = t + r * 256;
            int fout = e >> 2, q = e & 3;
            float4 v = ((const float4*)W)[fout * 32 + (g0 >> 2) + q];
            smW[(q * 4 + 0) * LDA + fout] = v.x;
            smW[(q * 4 + 1) * LDA + fout] = v.y;
            smW[(q * 4 + 2) * LDA + fout] = v.z;
            smW[(q * 4 + 3) * LDA + fout] = v.w;
        }
        __syncthreads();
#pragma unroll
        for (int gl = 0; gl < 16; gl++) {
            float4 b0 = *(float4*)&smW[gl * LDA + gb];
            float4 b1 = *(float4*)&smW[gl * LDA + gb + 4];
            float bv[8] = {b0.x, b0.y, b0.z, b0.w, b1.x, b1.y, b1.z, b1.w};
            float av[4];
#pragma unroll
            for (int i = 0; i < 4; i++) av[i] = smA[(mb + i) * LDA + g0 + gl];
#pragma unroll
            for (int i = 0; i < 4; i++)
#pragma unroll
                for (int j = 0; j < 8; j++)
                    acc[i][j] = fmaf(av[i], bv[j], acc[i][j]);
        }
    }
    __syncthreads();
}

__global__ __launch_bounds__(256)
void k_resmlp(const float* __restrict__ x, MlpArgs args, float* __restrict__ out)
{
    __shared__ float smA[64 * LDA];
    __shared__ float smW[16 * LDA];

    int ch = blockIdx.y;
    const float* wr = args.wr[ch];
    const float* brp = args.br[ch];
    const float* w1 = args.w1[ch];
    const float* b1p = args.b1[ch];
    float* dst = (ch == 0) ? out : (ch == 1) ? g_sfea : (ch == 2) ? g_pfea : g_dfea;

    int row0 = blockIdx.x * 64;
    int t = threadIdx.x;
    int tx = t & 15, ty = t >> 4;
    int mb = ty * 4, gb = tx * 8;

#pragma unroll
    for (int r = 0; r < 8; r++) {
        int e = t + r * 256;
        int m = e >> 5, c4 = e & 31;
        int gr = row0 + m;
        float4 v = make_float4(0.f, 0.f, 0.f, 0.f);
        if (gr < NATOM) v = ((const float4*)x)[gr * 32 + c4];
        float4 s = make_float4(siluf(v.x), siluf(v.y), siluf(v.z), siluf(v.w));
        *(float4*)&smA[m * LDA + c4 * 4] = s;
    }

    float acc[4][8];
    gemm_pass(wr, acc, smA, smW, t, mb, gb);

#pragma unroll
    for (int i = 0; i < 4; i++) {
        int gr = row0 + mb + i;
        float4 x0 = make_float4(0.f, 0.f, 0.f, 0.f), x1 = x0;
        if (gr < NATOM) {
            x0 = ((const float4*)x)[gr * 32 + (gb >> 2)];
            x1 = ((const float4*)x)[gr * 32 + (gb >> 2) + 1];
        }
        float xv[8] = {x0.x, x0.y, x0.z, x0.w, x1.x, x1.y, x1.z, x1.w};
#pragma unroll
        for (int j = 0; j < 8; j++) {
            float h = acc[i][j] + xv[j] + brp[gb + j];
            smA[(mb + i) * LDA + gb + j] = siluf(h);
        }
    }

    gemm_pass(w1, acc, smA, smW, t, mb, gb);

#pragma unroll
    for (int i = 0; i < 4; i++) {
        int gr = row0 + mb + i;
        if (gr < NATOM) {
            float4 o0 = make_float4(acc[i][0] + b1p[gb + 0], acc[i][1] + b1p[gb + 1],
                                    acc[i][2] + b1p[gb + 2], acc[i][3] + b1p[gb + 3]);
            float4 o1 = make_float4(acc[i][4] + b1p[gb + 4], acc[i][5] + b1p[gb + 5],
                                    acc[i][6] + b1p[gb + 6], acc[i][7] + b1p[gb + 7]);
            ((float4*)dst)[gr * 32 + (gb >> 2)] = o0;
            ((float4*)dst)[gr * 32 + (gb >> 2) + 1] = o1;
        }
    }
}

// ---------------- K3: env via tf32 mma ----------------
// One atom per 128-thread block iteration; persistent grid.
// Per atom:  E = G_ch @ B   (B = packed g tensors, cols [ch][a][j pad16])
//            epilogue: j-weighted reduce with gathered neighbor features.
__global__ __launch_bounds__(128)
void k_env_mma(const int* __restrict__ nbr,
               const float* __restrict__ gs, const float* __restrict__ gp,
               const float* __restrict__ gd,
               const float* __restrict__ Gs, const float* __restrict__ Gp,
               const float* __restrict__ Gd,
               float* __restrict__ out)
{
    __shared__ unsigned sBu[SB_FLOATS];          // 19456 B
    __shared__ float sFea[SFEA_FLOATS];          // 26112 B  [3][128][FEA_LD]

    int t = threadIdx.x;
    int w = t >> 5;                 // warp (0..3)
    int lane = t & 31;
    int gid = lane >> 2;            // 0..7
    int tig = lane & 3;             // 0..3

    // ---- A fragments (G matrices), atom-invariant: load once ----
    const float* Gtab[3] = {Gs, Gp, Gd};
    unsigned Afr[3][2][4][4];
#pragma unroll
    for (int ch = 0; ch < 3; ch++) {
        const float* G = Gtab[ch];
#pragma unroll
        for (int mt = 0; mt < 2; mt++) {
#pragma unroll
            for (int k4 = 0; k4 < 4; k4++) {
                int r0 = w * 32 + mt * 16 + gid;
                int c0 = k4 * 8 + tig;
                Afr[ch][mt][k4][0] = tf32r(G[r0 * 32 + c0]);
                Afr[ch][mt][k4][1] = tf32r(G[(r0 + 8) * 32 + c0]);
                Afr[ch][mt][k4][2] = tf32r(G[r0 * 32 + c0 + 4]);
                Afr[ch][mt][k4][3] = tf32r(G[(r0 + 8) * 32 + c0 + 4]);
            }
        }
    }

    const float4* gs4 = (const float4*)gs;
    const float4* gp4 = (const float4*)gp;
    const float4* gd4 = (const float4*)gd;

    for (int n = blockIdx.x; n < NATOM; n += gridDim.x) {
        // ---------- staging ----------
        int jn[NNJ];
#pragma unroll
        for (int j = 0; j < NNJ; j++) jn[j] = nbr[n * NNJ + j];

        // zero the pad columns (j=12..15 of each of 9 groups): 32k x 36 cols
#pragma unroll
        for (int r = 0; r < 9; r++) {
            int e = t + r * 128;                  // 0..1151
            int k = e / 36, pc = e % 36;
            int g = pc >> 2, jj = pc & 3;
            sBu[k * LDB + g * 16 + 12 + jj] = 0u;
        }
        // gs -> cols [0,12): sB[k][j]
        if (t < 96) {
            float4 v = gs4[(size_t)n * 96 + t];
            int j = t >> 3, q = t & 7;
            int base = (q * 4) * LDB + j;
            sBu[base]            = tf32r(v.x);
            sBu[base + LDB]      = tf32r(v.y);
            sBu[base + 2 * LDB]  = tf32r(v.z);
            sBu[base + 3 * LDB]  = tf32r(v.w);
        }
        // gp -> cols 16 + a*16 + j
#pragma unroll
        for (int r = 0; r < 3; r++) {
            int e = t + r * 128;
            if (e < 288) {
                float4 v = gp4[(size_t)n * 288 + e];
                float vv[4] = {v.x, v.y, v.z, v.w};
#pragma unroll
                for (int u = 0; u < 4; u++) {
                    int idx = e * 4 + u;
                    int j = idx / 96, rr = idx % 96;
                    int k = rr / 3, a = rr % 3;
                    sBu[k * LDB + 16 + a * 16 + j] = tf32r(vv[u]);
                }
            }
        }
        // gd -> cols 64 + a*16 + j
#pragma unroll
        for (int r = 0; r < 4; r++) {
            int e = t + r * 128;
            if (e < 480) {
                float4 v = gd4[(size_t)n * 480 + e];
                float vv[4] = {v.x, v.y, v.z, v.w};
#pragma unroll
                for (int u = 0; u < 4; u++) {
                    int idx = e * 4 + u;
                    int j = idx / 160, rr = idx % 160;
                    int k = rr / 5, a = rr % 5;
                    sBu[k * LDB + 64 + a * 16 + j] = tf32r(vv[u]);
                }
            }
        }
        // neighbor feature gather: sFea[ch][f=t][j]
        {
            const float* feaP[3] = {g_sfea, g_pfea, g_dfea};
#pragma unroll
            for (int ch = 0; ch < 3; ch++) {
                float* row = sFea + ch * (128 * FEA_LD) + t * FEA_LD;
#pragma unroll
                for (int j = 0; j < NNJ; j++)
                    row[j] = feaP[ch][(size_t)jn[j] * FD + t];
#pragma unroll
                for (int j = NNJ; j < 16; j++) row[j] = 0.f;
            }
        }

        __syncthreads();

        // ---------- compute ----------
        float P[2][2][9];
#pragma unroll
        for (int mt = 0; mt < 2; mt++)
#pragma unroll
            for (int rr = 0; rr < 2; rr++)
#pragma unroll
                for (int q = 0; q < 9; q++) P[mt][rr][q] = 0.f;

#pragma unroll
        for (int ch = 0; ch < 3; ch++) {
            const int NA = (ch == 0) ? 1 : (ch == 1) ? 3 : 5;
            const int CB = (ch == 0) ? 0 : (ch == 1) ? 16 : 64;
            const int PB = (ch == 0) ? 0 : (ch == 1) ? 1 : 4;
#pragma unroll
            for (int a = 0; a < NA; a++) {
#pragma unroll
                for (int half = 0; half < 2; half++) {
                    int cb = CB + a * 16 + half * 8;
                    unsigned bf[8];
#pragma unroll
                    for (int k4 = 0; k4 < 4; k4++) {
                        bf[2 * k4]     = sBu[(k4 * 8 + tig) * LDB + cb + gid];
                        bf[2 * k4 + 1] = sBu[(k4 * 8 + tig + 4) * LDB + cb + gid];
                    }
                    int j0 = half * 8 + 2 * tig;
#pragma unroll
                    for (int mt = 0; mt < 2; mt++) {
                        float C[4] = {0.f, 0.f, 0.f, 0.f};
#pragma unroll
                        for (int k4 = 0; k4 < 4; k4++)
                            mma_tf32(C, Afr[ch][mt][k4], bf[2 * k4], bf[2 * k4 + 1]);
                        int r = w * 32 + mt * 16 + gid;
                        const float* fr0 = sFea + ch * (128 * FEA_LD) + r * FEA_LD;
                        const float* fr1 = fr0 + 8 * FEA_LD;
                        P[mt][0][PB + a] += C[0] * fr0[j0] + C[1] * fr0[j0 + 1];
                        P[mt][1][PB + a] += C[2] * fr1[j0] + C[3] * fr1[j0 + 1];
                    }
                }
            }
        }

        // ---------- reduce over quad + store ----------
#pragma unroll
        for (int mt = 0; mt < 2; mt++) {
#pragma unroll
            for (int rr = 0; rr < 2; rr++) {
#pragma unroll
                for (int q = 0; q < 9; q++) {
                    float v = P[mt][rr][q];
                    v += __shfl_xor_sync(0xffffffffu, v, 1);
                    v += __shfl_xor_sync(0xffffffffu, v, 2);
                    if (tig == 0) {
                        int r = w * 32 + mt * 16 + rr * 8 + gid;
                        if (q == 0)
                            out[(size_t)n * FD + r] += v;
                        else if (q < 4)
                            g_allp[((size_t)n * 3 + (q - 1)) * FD + r] = v;
                        else
                            g_alld[((size_t)n * 5 + (q - 4)) * FD + r] = v;
                    }
                }
            }
        }

        __syncthreads();   // protect sBu/sFea before next iteration's staging
    }
}

// ---------------- K4: rowdot[r] = v_r . (M v_r) ----------------
__global__ __launch_bounds__(256)
void k_quad(int which)
{
    const float* V = which ? g_alld : g_allp;
    const float* M = which ? g_Md : g_Mp;
    float* rowdot = which ? g_rowd : g_rowp;
    int R = which ? NATOM * 5 : NATOM * 3;

    __shared__ float smA[64 * LDA];
    __shared__ float smW[16 * LDA];

    int row0 = blockIdx.x * 64;
    int t = threadIdx.x;
    int tx = t & 15, ty = t >> 4;
    int mb = ty * 4, gb = tx * 8;

#pragma unroll
    for (int r = 0; r < 8; r++) {
        int e = t + r * 256;
        int m = e >> 5, c4 = e & 31;
        int gr = row0 + m;
        float4 v = make_float4(0.f, 0.f, 0.f, 0.f);
        if (gr < R) v = ((const float4*)V)[gr * 32 + c4];
        *(float4*)&smA[m * LDA + c4 * 4] = v;
    }

    float acc[4][8];
#pragma unroll
    for (int i = 0; i < 4; i++)
#pragma unroll
        for (int j = 0; j < 8; j++) acc[i][j] = 0.f;

    for (int f0 = 0; f0 < FD; f0 += 16) {
        __syncthreads();
#pragma unroll
        for (int r = 0; r < 2; r++) {
            int e = t + r * 256;
            int fl = e >> 5, q = e & 31;
            float4 v = ((const float4*)M)[(f0 + fl) * 32 + q];
            *(float4*)&smW[fl * LDA + q * 4] = v;
        }
        __syncthreads();
#pragma unroll
        for (int fl = 0; fl < 16; fl++) {
            float4 b0 = *(float4*)&smW[fl * LDA + gb];
            float4 b1 = *(float4*)&smW[fl * LDA + gb + 4];
            float bv[8] = {b0.x, b0.y, b0.z, b0.w, b1.x, b1.y, b1.z, b1.w};
            float av[4];
#pragma unroll
            for (int i = 0; i < 4; i++) av[i] = smA[(mb + i) * LDA + f0 + fl];
#pragma unroll
            for (int i = 0; i < 4; i++)
#pragma unroll
                for (int j = 0; j < 8; j++)
                    acc[i][j] = fmaf(av[i], bv[j], acc[i][j]);
        }
    }

#pragma unroll
    for (int i = 0; i < 4; i++) {
        float d = 0.f;
#pragma unroll
        for (int j = 0; j < 8; j++)
            d = fmaf(acc[i][j], smA[(mb + i) * LDA + gb + j], d);
#pragma unroll
        for (int o = 8; o > 0; o >>= 1)
            d += __shfl_down_sync(0xffffffffu, d, o, 16);
        int gr = row0 + mb + i;
        if (tx == 0 && gr < R) rowdot[gr] = d;
    }
}

// ---------------- K5: broadcast scalar add ----------------
__global__ void k_final(float* __restrict__ out)
{
    int idx = blockIdx.x * blockDim.x + threadIdx.x;
    if (idx >= NATOM * FD) return;
    int n = idx >> 7;
    float s = g_rowp[n * 3 + 0] + g_rowp[n * 3 + 1] + g_rowp[n * 3 + 2]
            + g_rowd[n * 5 + 0] + g_rowd[n * 5 + 1] + g_rowd[n * 5 + 2]
            + g_rowd[n * 5 + 3] + g_rowd[n * 5 + 4];
    out[idx] += s;
}

// ---------------- launch ----------------
extern "C" void kernel_launch(void* const* d_in, const int* in_sizes, int n_in,
                              void* d_out, int out_size)
{
    const float* atom = (const float*)d_in[0];
    const int*   nbr  = (const int*)d_in[1];
    const float* gs   = (const float*)d_in[2];
    const float* gp   = (const float*)d_in[3];
    const float* gd   = (const float*)d_in[4];
    const float* Gs   = (const float*)d_in[5];
    const float* Gp   = (const float*)d_in[6];
    const float* Gd   = (const float*)d_in[7];
    const float* P1   = (const float*)d_in[8];
    const float* P2   = (const float*)d_in[9];
    const float* D1   = (const float*)d_in[10];
    const float* D2   = (const float*)d_in[11];
    float* out = (float*)d_out;

    MlpArgs a;
    for (int ch = 0; ch < 4; ch++) {
        a.wr[ch] = (const float*)d_in[12 + ch * 4 + 0];
        a.br[ch] = (const float*)d_in[12 + ch * 4 + 1];
        a.w1[ch] = (const float*)d_in[12 + ch * 4 + 2];
        a.b1[ch] = (const float*)d_in[12 + ch * 4 + 3];
    }

    k_mmt<<<dim3(16, 2), 128>>>(P1, P2, D1, D2);
    k_resmlp<<<dim3((NATOM + 63) / 64, 4), 256>>>(atom, a, out);
    k_env_mma<<<592, 128>>>(nbr, gs, gp, gd, Gs, Gp, Gd, out);
    k_quad<<<(NATOM * 3 + 63) / 64, 256>>>(0);
    k_quad<<<(NATOM * 5 + 63) / 64, 256>>>(1);
    k_final<<<(NATOM * FD + 255) / 256, 256>>>(out);
}

// round 7
// speedup vs baseline: 1.6430x; 1.1064x over previous
#include <cuda_runtime.h>

#define NATOM 30000
#define NNJ 12
#define KD 32
#define FD 128
#define LDA 132

// sB layout: [32 k][152 cols]; cols: s [0,16), p a*16+[16,64), d a*16+[64,144), pads zeroed
#define LDB 152
#define SB_FLOATS (32 * LDB)           // 4864
#define FEA_LD 17
#define SFEA_FLOATS (3 * 128 * FEA_LD) // 6528

// ---------------- device scratch ----------------
__device__ float g_sfea[NATOM * FD];
__device__ float g_pfea[NATOM * FD];
__device__ float g_dfea[NATOM * FD];
__device__ float g_allp[NATOM * 3 * FD];   // [n][a][f]
__device__ float g_alld[NATOM * 5 * FD];   // [n][a][f]
__device__ float g_Mp[FD * FD];            // P1 @ P2^T
__device__ float g_Md[FD * FD];            // D1 @ D2^T
__device__ float g_rowp[NATOM * 3];
__device__ float g_rowd[NATOM * 5];

__device__ __forceinline__ float siluf(float x) {
    return x / (1.0f + __expf(-x));
}

__device__ __forceinline__ unsigned tf32r(float x) {
    unsigned u;
    asm("cvt.rna.tf32.f32 %0, %1;" : "=r"(u) : "f"(x));
    return u;
}

__device__ __forceinline__ void mma_tf32(float c[4], const unsigned a[4],
                                         unsigned b0, unsigned b1) {
    asm volatile(
        "mma.sync.aligned.m16n8k8.row.col.f32.tf32.tf32.f32 "
        "{%0,%1,%2,%3},{%4,%5,%6,%7},{%8,%9},{%0,%1,%2,%3};"
        : "+f"(c[0]), "+f"(c[1]), "+f"(c[2]), "+f"(c[3])
        : "r"(a[0]), "r"(a[1]), "r"(a[2]), "r"(a[3]), "r"(b0), "r"(b1));
}

// ---------------- K1: Mp = P1 @ P2^T, Md = D1 @ D2^T ----------------
__global__ __launch_bounds__(128)
void k_mmt(const float* __restrict__ P1, const float* __restrict__ P2,
           const float* __restrict__ D1, const float* __restrict__ D2)
{
    const float* A = blockIdx.y ? D1 : P1;
    const float* B = blockIdx.y ? D2 : P2;
    float* M = blockIdx.y ? g_Md : g_Mp;

    __shared__ float smA[8 * FD];
    __shared__ float smB[16 * LDA];
    int t = threadIdx.x;
    int i0 = blockIdx.x * 8;

#pragma unroll
    for (int r = 0; r < 2; r++) {
        int e = t + r * 128;
        ((float4*)smA)[e] = ((const float4*)A)[i0 * 32 + e];
    }

    float acc[8];
#pragma unroll
    for (int i = 0; i < 8; i++) acc[i] = 0.f;

    for (int g0 = 0; g0 < FD; g0 += 16) {
        __syncthreads();
#pragma unroll
        for (int r = 0; r < 4; r++) {
            int e = t + r * 128;
            int j = e >> 2, q = e & 3;
            float4 v = ((const float4*)B)[j * 32 + (g0 >> 2) + q];
            smB[(q * 4 + 0) * LDA + j] = v.x;
            smB[(q * 4 + 1) * LDA + j] = v.y;
            smB[(q * 4 + 2) * LDA + j] = v.z;
            smB[(q * 4 + 3) * LDA + j] = v.w;
        }
        __syncthreads();
#pragma unroll
        for (int gl = 0; gl < 16; gl++) {
            float b = smB[gl * LDA + t];
#pragma unroll
            for (int i = 0; i < 8; i++)
                acc[i] = fmaf(smA[i * FD + g0 + gl], b, acc[i]);
        }
    }
#pragma unroll
    for (int i = 0; i < 8; i++) M[(i0 + i) * FD + t] = acc[i];
}

// ---------------- K2: fused ResMLP via tf32 mma ----------------
// Block: 64 rows x 128 cols, 256 threads = 8 warps (4 m-tiles x 2 n-halves).
struct MlpArgs {
    const float* wr[4]; const float* br[4];
    const float* w1[4]; const float* b1[4];
};

// acc[nt][4] += smA(rows m-tile) x W^T(cols nhalf)
__device__ __forceinline__ void mma_gemm_pass(const float* __restrict__ W,
                                              float acc[8][4],
                                              const unsigned* smA,
                                              int mt, int nh, int gid, int tig)
{
#pragma unroll
    for (int nt = 0; nt < 8; nt++)
#pragma unroll
        for (int c = 0; c < 4; c++) acc[nt][c] = 0.f;

    for (int k0 = 0; k0 < FD; k0 += 8) {
        unsigned a[4];
        int r0 = mt * 16 + gid;
        a[0] = smA[r0 * LDA + k0 + tig];
        a[1] = smA[(r0 + 8) * LDA + k0 + tig];
        a[2] = smA[r0 * LDA + k0 + tig + 4];
        a[3] = smA[(r0 + 8) * LDA + k0 + tig + 4];
#pragma unroll
        for (int nt = 0; nt < 8; nt++) {
            int n0 = nh * 64 + nt * 8;
            unsigned b0 = tf32r(W[(n0 + gid) * FD + k0 + tig]);
            unsigned b1 = tf32r(W[(n0 + gid) * FD + k0 + tig + 4]);
            mma_tf32(acc[nt], a, b0, b1);
        }
    }
}

__global__ __launch_bounds__(256)
void k_resmlp_mma(const float* __restrict__ x, MlpArgs args, float* __restrict__ out)
{
    __shared__ unsigned smA[64 * LDA];   // 33792 B, tf32 bits

    int ch = blockIdx.y;
    const float* wr = args.wr[ch];
    const float* brp = args.br[ch];
    const float* w1 = args.w1[ch];
    const float* b1p = args.b1[ch];
    float* dst = (ch == 0) ? out : (ch == 1) ? g_sfea : (ch == 2) ? g_pfea : g_dfea;

    int row0 = blockIdx.x * 64;
    int t = threadIdx.x;
    int w = t >> 5, lane = t & 31;
    int mt = w & 3, nh = w >> 2;
    int gid = lane >> 2, tig = lane & 3;

    // stage silu(x) as tf32
#pragma unroll
    for (int r = 0; r < 8; r++) {
        int e = t + r * 256;
        int m = e >> 5, c4 = e & 31;
        int gr = row0 + m;
        float4 v = make_float4(0.f, 0.f, 0.f, 0.f);
        if (gr < NATOM) v = ((const float4*)x)[gr * 32 + c4];
        smA[m * LDA + c4 * 4 + 0] = tf32r(siluf(v.x));
        smA[m * LDA + c4 * 4 + 1] = tf32r(siluf(v.y));
        smA[m * LDA + c4 * 4 + 2] = tf32r(siluf(v.z));
        smA[m * LDA + c4 * 4 + 3] = tf32r(siluf(v.w));
    }
    __syncthreads();

    float acc[8][4];
    mma_gemm_pass(wr, acc, smA, mt, nh, gid, tig);
    __syncthreads();   // all warps done reading smA

    // epilogue 1: h = acc + x + br ; smA = tf32(silu(h))
    {
        int r0 = row0 + mt * 16 + gid;
        int r1 = r0 + 8;
#pragma unroll
        for (int nt = 0; nt < 8; nt++) {
            int c = nh * 64 + nt * 8 + 2 * tig;
            float2 br2 = *(const float2*)&brp[c];
            float2 x0 = make_float2(0.f, 0.f), x1 = x0;
            if (r0 < NATOM) x0 = *(const float2*)&x[r0 * FD + c];
            if (r1 < NATOM) x1 = *(const float2*)&x[r1 * FD + c];
            int lr0 = mt * 16 + gid, lr1 = lr0 + 8;
            smA[lr0 * LDA + c]     = tf32r(siluf(acc[nt][0] + x0.x + br2.x));
            smA[lr0 * LDA + c + 1] = tf32r(siluf(acc[nt][1] + x0.y + br2.y));
            smA[lr1 * LDA + c]     = tf32r(siluf(acc[nt][2] + x1.x + br2.x));
            smA[lr1 * LDA + c + 1] = tf32r(siluf(acc[nt][3] + x1.y + br2.y));
        }
    }
    __syncthreads();

    mma_gemm_pass(w1, acc, smA, mt, nh, gid, tig);

    // epilogue 2: out = acc + b1
    {
        int r0 = row0 + mt * 16 + gid;
        int r1 = r0 + 8;
#pragma unroll
        for (int nt = 0; nt < 8; nt++) {
            int c = nh * 64 + nt * 8 + 2 * tig;
            float2 b2 = *(const float2*)&b1p[c];
            if (r0 < NATOM)
                *(float2*)&dst[r0 * FD + c] =
                    make_float2(acc[nt][0] + b2.x, acc[nt][1] + b2.y);
            if (r1 < NATOM)
                *(float2*)&dst[r1 * FD + c] =
                    make_float2(acc[nt][2] + b2.x, acc[nt][3] + b2.y);
        }
    }
}

// ---------------- K3: env via tf32 mma ----------------
__global__ __launch_bounds__(128)
void k_env_mma(const int* __restrict__ nbr,
               const float* __restrict__ gs, const float* __restrict__ gp,
               const float* __restrict__ gd,
               const float* __restrict__ Gs, const float* __restrict__ Gp,
               const float* __restrict__ Gd,
               float* __restrict__ out)
{
    __shared__ unsigned sBu[SB_FLOATS];
    __shared__ float sFea[SFEA_FLOATS];

    int t = threadIdx.x;
    int w = t >> 5;
    int lane = t & 31;
    int gid = lane >> 2;
    int tig = lane & 3;

    const float* Gtab[3] = {Gs, Gp, Gd};
    unsigned Afr[3][2][4][4];
#pragma unroll
    for (int ch = 0; ch < 3; ch++) {
        const float* G = Gtab[ch];
#pragma unroll
        for (int mt = 0; mt < 2; mt++) {
#pragma unroll
            for (int k4 = 0; k4 < 4; k4++) {
                int r0 = w * 32 + mt * 16 + gid;
                int c0 = k4 * 8 + tig;
                Afr[ch][mt][k4][0] = tf32r(G[r0 * 32 + c0]);
                Afr[ch][mt][k4][1] = tf32r(G[(r0 + 8) * 32 + c0]);
                Afr[ch][mt][k4][2] = tf32r(G[r0 * 32 + c0 + 4]);
                Afr[ch][mt][k4][3] = tf32r(G[(r0 + 8) * 32 + c0 + 4]);
            }
        }
    }

    const float4* gs4 = (const float4*)gs;
    const float4* gp4 = (const float4*)gp;
    const float4* gd4 = (const float4*)gd;

    for (int n = blockIdx.x; n < NATOM; n += gridDim.x) {
        int jn[NNJ];
#pragma unroll
        for (int j = 0; j < NNJ; j++) jn[j] = nbr[n * NNJ + j];

#pragma unroll
        for (int r = 0; r < 9; r++) {
            int e = t + r * 128;
            int k = e / 36, pc = e % 36;
            int g = pc >> 2, jj = pc & 3;
            sBu[k * LDB + g * 16 + 12 + jj] = 0u;
        }
        if (t < 96) {
            float4 v = gs4[(size_t)n * 96 + t];
            int j = t >> 3, q = t & 7;
            int base = (q * 4) * LDB + j;
            sBu[base]            = tf32r(v.x);
            sBu[base + LDB]      = tf32r(v.y);
            sBu[base + 2 * LDB]  = tf32r(v.z);
            sBu[base + 3 * LDB]  = tf32r(v.w);
        }
#pragma unroll
        for (int r = 0; r < 3; r++) {
            int e = t + r * 128;
            if (e < 288) {
                float4 v = gp4[(size_t)n * 288 + e];
                float vv[4] = {v.x, v.y, v.z, v.w};
#pragma unroll
                for (int u = 0; u < 4; u++) {
                    int idx = e * 4 + u;
                    int j = idx / 96, rr = idx % 96;
                    int k = rr / 3, a = rr % 3;
                    sBu[k * LDB + 16 + a * 16 + j] = tf32r(vv[u]);
                }
            }
        }
#pragma unroll
        for (int r = 0; r < 4; r++) {
            int e = t + r * 128;
            if (e < 480) {
                float4 v = gd4[(size_t)n * 480 + e];
                float vv[4] = {v.x, v.y, v.z, v.w};
#pragma unroll
                for (int u = 0; u < 4; u++) {
                    int idx = e * 4 + u;
                    int j = idx / 160, rr = idx % 160;
                    int k = rr / 5, a = rr % 5;
                    sBu[k * LDB + 64 + a * 16 + j] = tf32r(vv[u]);
                }
            }
        }
        {
            const float* feaP[3] = {g_sfea, g_pfea, g_dfea};
#pragma unroll
            for (int ch = 0; ch < 3; ch++) {
                float* row = sFea + ch * (128 * FEA_LD) + t * FEA_LD;
#pragma unroll
                for (int j = 0; j < NNJ; j++)
                    row[j] = feaP[ch][(size_t)jn[j] * FD + t];
#pragma unroll
                for (int j = NNJ; j < 16; j++) row[j] = 0.f;
            }
        }

        __syncthreads();

        float P[2][2][9];
#pragma unroll
        for (int mt = 0; mt < 2; mt++)
#pragma unroll
            for (int rr = 0; rr < 2; rr++)
#pragma unroll
                for (int q = 0; q < 9; q++) P[mt][rr][q] = 0.f;

#pragma unroll
        for (int ch = 0; ch < 3; ch++) {
            const int NA = (ch == 0) ? 1 : (ch == 1) ? 3 : 5;
            const int CB = (ch == 0) ? 0 : (ch == 1) ? 16 : 64;
            const int PB = (ch == 0) ? 0 : (ch == 1) ? 1 : 4;
#pragma unroll
            for (int a = 0; a < NA; a++) {
#pragma unroll
                for (int half = 0; half < 2; half++) {
                    int cb = CB + a * 16 + half * 8;
                    unsigned bf[8];
#pragma unroll
                    for (int k4 = 0; k4 < 4; k4++) {
                        bf[2 * k4]     = sBu[(k4 * 8 + tig) * LDB + cb + gid];
                        bf[2 * k4 + 1] = sBu[(k4 * 8 + tig + 4) * LDB + cb + gid];
                    }
                    int j0 = half * 8 + 2 * tig;
#pragma unroll
                    for (int mt = 0; mt < 2; mt++) {
                        float C[4] = {0.f, 0.f, 0.f, 0.f};
#pragma unroll
                        for (int k4 = 0; k4 < 4; k4++)
                            mma_tf32(C, Afr[ch][mt][k4], bf[2 * k4], bf[2 * k4 + 1]);
                        int r = w * 32 + mt * 16 + gid;
                        const float* fr0 = sFea + ch * (128 * FEA_LD) + r * FEA_LD;
                        const float* fr1 = fr0 + 8 * FEA_LD;
                        P[mt][0][PB + a] += C[0] * fr0[j0] + C[1] * fr0[j0 + 1];
                        P[mt][1][PB + a] += C[2] * fr1[j0] + C[3] * fr1[j0 + 1];
                    }
                }
            }
        }

#pragma unroll
        for (int mt = 0; mt < 2; mt++) {
#pragma unroll
            for (int rr = 0; rr < 2; rr++) {
#pragma unroll
                for (int q = 0; q < 9; q++) {
                    float v = P[mt][rr][q];
                    v += __shfl_xor_sync(0xffffffffu, v, 1);
                    v += __shfl_xor_sync(0xffffffffu, v, 2);
                    if (tig == 0) {
                        int r = w * 32 + mt * 16 + rr * 8 + gid;
                        if (q == 0)
                            out[(size_t)n * FD + r] += v;
                        else if (q < 4)
                            g_allp[((size_t)n * 3 + (q - 1)) * FD + r] = v;
                        else
                            g_alld[((size_t)n * 5 + (q - 4)) * FD + r] = v;
                    }
                }
            }
        }

        __syncthreads();
    }
}

// ---------------- K4: rowdot[r] = v_r . (M v_r) via tf32 mma ----------------
__global__ __launch_bounds__(256)
void k_quad_mma(int which)
{
    const float* V = which ? g_alld : g_allp;
    const float* M = which ? g_Md : g_Mp;
    float* rowdot = which ? g_rowd : g_rowp;
    int R = which ? NATOM * 5 : NATOM * 3;

    __shared__ unsigned smA[64 * LDA];   // tf32 bits of V tile
    __shared__ float sPart[2][4][16];

    int row0 = blockIdx.x * 64;
    int t = threadIdx.x;
    int w = t >> 5, lane = t & 31;
    int mt = w & 3, nh = w >> 2;
    int gid = lane >> 2, tig = lane & 3;

    // stage V tile as tf32
#pragma unroll
    for (int r = 0; r < 8; r++) {
        int e = t + r * 256;
        int m = e >> 5, c4 = e & 31;
        int gr = row0 + m;
        float4 v = make_float4(0.f, 0.f, 0.f, 0.f);
        if (gr < R) v = ((const float4*)V)[gr * 32 + c4];
        smA[m * LDA + c4 * 4 + 0] = tf32r(v.x);
        smA[m * LDA + c4 * 4 + 1] = tf32r(v.y);
        smA[m * LDA + c4 * 4 + 2] = tf32r(v.z);
        smA[m * LDA + c4 * 4 + 3] = tf32r(v.w);
    }
    __syncthreads();

    float acc[8][4];
#pragma unroll
    for (int nt = 0; nt < 8; nt++)
#pragma unroll
        for (int c = 0; c < 4; c++) acc[nt][c] = 0.f;

    for (int k0 = 0; k0 < FD; k0 += 8) {
        unsigned a[4];
        int r0 = mt * 16 + gid;
        a[0] = smA[r0 * LDA + k0 + tig];
        a[1] = smA[(r0 + 8) * LDA + k0 + tig];
        a[2] = smA[r0 * LDA + k0 + tig + 4];
        a[3] = smA[(r0 + 8) * LDA + k0 + tig + 4];
#pragma unroll
        for (int nt = 0; nt < 8; nt++) {
            int n0 = nh * 64 + nt * 8;
            // B element (k=f, n=g) = M[f][g]
            unsigned b0 = tf32r(M[(k0 + tig) * FD + n0 + gid]);
            unsigned b1 = tf32r(M[(k0 + tig + 4) * FD + n0 + gid]);
            mma_tf32(acc[nt], a, b0, b1);
        }
    }

    // fused row dot vs smem V (tf32-truncated)
    float d0 = 0.f, d1 = 0.f;
    {
        int lr0 = mt * 16 + gid, lr1 = lr0 + 8;
#pragma unroll
        for (int nt = 0; nt < 8; nt++) {
            int c = nh * 64 + nt * 8 + 2 * tig;
            float v00 = __uint_as_float(smA[lr0 * LDA + c]);
            float v01 = __uint_as_float(smA[lr0 * LDA + c + 1]);
            float v10 = __uint_as_float(smA[lr1 * LDA + c]);
            float v11 = __uint_as_float(smA[lr1 * LDA + c + 1]);
            d0 = fmaf(acc[nt][0], v00, fmaf(acc[nt][1], v01, d0));
            d1 = fmaf(acc[nt][2], v10, fmaf(acc[nt][3], v11, d1));
        }
    }
    d0 += __shfl_xor_sync(0xffffffffu, d0, 1);
    d0 += __shfl_xor_sync(0xffffffffu, d0, 2);
    d1 += __shfl_xor_sync(0xffffffffu, d1, 1);
    d1 += __shfl_xor_sync(0xffffffffu, d1, 2);
    if (tig == 0) {
        sPart[nh][mt][gid] = d0;
        sPart[nh][mt][gid + 8] = d1;
    }
    __syncthreads();

    if (t < 64) {
        int mtt = t >> 4, r = t & 15;
        int gr = row0 + mtt * 16 + r;
        if (gr < R) rowdot[gr] = sPart[0][mtt][r] + sPart[1][mtt][r];
    }
}

// ---------------- K5: broadcast scalar add ----------------
__global__ void k_final(float* __restrict__ out)
{
    int idx = blockIdx.x * blockDim.x + threadIdx.x;
    if (idx >= NATOM * FD) return;
    int n = idx >> 7;
    float s = g_rowp[n * 3 + 0] + g_rowp[n * 3 + 1] + g_rowp[n * 3 + 2]
            + g_rowd[n * 5 + 0] + g_rowd[n * 5 + 1] + g_rowd[n * 5 + 2]
            + g_rowd[n * 5 + 3] + g_rowd[n * 5 + 4];
    out[idx] += s;
}

// ---------------- launch ----------------
extern "C" void kernel_launch(void* const* d_in, const int* in_sizes, int n_in,
                              void* d_out, int out_size)
{
    const float* atom = (const float*)d_in[0];
    const int*   nbr  = (const int*)d_in[1];
    const float* gs   = (const float*)d_in[2];
    const float* gp   = (const float*)d_in[3];
    const float* gd   = (const float*)d_in[4];
    const float* Gs   = (const float*)d_in[5];
    const float* Gp   = (const float*)d_in[6];
    const float* Gd   = (const float*)d_in[7];
    const float* P1   = (const float*)d_in[8];
    const float* P2   = (const float*)d_in[9];
    const float* D1   = (const float*)d_in[10];
    const float* D2   = (const float*)d_in[11];
    float* out = (float*)d_out;

    MlpArgs a;
    for (int ch = 0; ch < 4; ch++) {
        a.wr[ch] = (const float*)d_in[12 + ch * 4 + 0];
        a.br[ch] = (const float*)d_in[12 + ch * 4 + 1];
        a.w1[ch] = (const float*)d_in[12 + ch * 4 + 2];
        a.b1[ch] = (const float*)d_in[12 + ch * 4 + 3];
    }

    k_mmt<<<dim3(16, 2), 128>>>(P1, P2, D1, D2);
    k_resmlp_mma<<<dim3((NATOM + 63) / 64, 4), 256>>>(atom, a, out);
    k_env_mma<<<592, 128>>>(nbr, gs, gp, gd, Gs, Gp, Gd, out);
    k_quad_mma<<<(NATOM * 3 + 63) / 64, 256>>>(0);
    k_quad_mma<<<(NATOM * 5 + 63) / 64, 256>>>(1);
    k_final<<<(NATOM * FD + 255) / 256, 256>>>(out);
}

// round 8
// speedup vs baseline: 1.7784x; 1.0825x over previous
#include <cuda_runtime.h>

#define NATOM 30000
#define NNJ 12
#define KD 32
#define FD 128
#define LDA 132

// sB layout: [32 k][152 cols]; cols: s [0,16), p a*16+[16,64), d a*16+[64,144), pads zeroed
#define LDB 152
#define SB_FLOATS (32 * LDB)           // 4864
#define FEA_LD 17
#define SFEA_FLOATS (3 * 128 * FEA_LD) // 6528

// ---------------- device scratch ----------------
__device__ float g_sfea[NATOM * FD];
__device__ float g_pfea[NATOM * FD];
__device__ float g_dfea[NATOM * FD];
__device__ float g_allp[NATOM * 3 * FD];   // [n][a][f]
__device__ float g_alld[NATOM * 5 * FD];   // [n][a][f]
__device__ float g_Mp[FD * FD];            // P1 @ P2^T
__device__ float g_Md[FD * FD];            // D1 @ D2^T
__device__ float g_rowp[NATOM * 3];
__device__ float g_rowd[NATOM * 5];

__device__ __forceinline__ float siluf(float x) {
    return x / (1.0f + __expf(-x));
}

__device__ __forceinline__ unsigned tf32r(float x) {
    unsigned u;
    asm("cvt.rna.tf32.f32 %0, %1;" : "=r"(u) : "f"(x));
    return u;
}

__device__ __forceinline__ void mma_tf32(float c[4], const unsigned a[4],
                                         unsigned b0, unsigned b1) {
    asm volatile(
        "mma.sync.aligned.m16n8k8.row.col.f32.tf32.tf32.f32 "
        "{%0,%1,%2,%3},{%4,%5,%6,%7},{%8,%9},{%0,%1,%2,%3};"
        : "+f"(c[0]), "+f"(c[1]), "+f"(c[2]), "+f"(c[3])
        : "r"(a[0]), "r"(a[1]), "r"(a[2]), "r"(a[3]), "r"(b0), "r"(b1));
}

// ---------------- K1: Mp = P1 @ P2^T, Md = D1 @ D2^T ----------------
__global__ __launch_bounds__(128)
void k_mmt(const float* __restrict__ P1, const float* __restrict__ P2,
           const float* __restrict__ D1, const float* __restrict__ D2)
{
    const float* A = blockIdx.y ? D1 : P1;
    const float* B = blockIdx.y ? D2 : P2;
    float* M = blockIdx.y ? g_Md : g_Mp;

    __shared__ float smA[8 * FD];
    __shared__ float smB[16 * LDA];
    int t = threadIdx.x;
    int i0 = blockIdx.x * 8;

#pragma unroll
    for (int r = 0; r < 2; r++) {
        int e = t + r * 128;
        ((float4*)smA)[e] = ((const float4*)A)[i0 * 32 + e];
    }

    float acc[8];
#pragma unroll
    for (int i = 0; i < 8; i++) acc[i] = 0.f;

    for (int g0 = 0; g0 < FD; g0 += 16) {
        __syncthreads();
#pragma unroll
        for (int r = 0; r < 4; r++) {
            int e = t + r * 128;
            int j = e >> 2, q = e & 3;
            float4 v = ((const float4*)B)[j * 32 + (g0 >> 2) + q];
            smB[(q * 4 + 0) * LDA + j] = v.x;
            smB[(q * 4 + 1) * LDA + j] = v.y;
            smB[(q * 4 + 2) * LDA + j] = v.z;
            smB[(q * 4 + 3) * LDA + j] = v.w;
        }
        __syncthreads();
#pragma unroll
        for (int gl = 0; gl < 16; gl++) {
            float b = smB[gl * LDA + t];
#pragma unroll
            for (int i = 0; i < 8; i++)
                acc[i] = fmaf(smA[i * FD + g0 + gl], b, acc[i]);
        }
    }
#pragma unroll
    for (int i = 0; i < 8; i++) M[(i0 + i) * FD + t] = acc[i];
}

// ---------------- K2: fused ResMLP via tf32 mma, smem-staged W ----------------
// Block: 64 rows x 128 cols, 256 threads = 8 warps (4 m-tiles x 2 n-halves).
struct MlpArgs {
    const float* wr[4]; const float* br[4];
    const float* w1[4]; const float* b1[4];
};

// acc[nt][4] += smA(rows m-tile) x W^T(cols nhalf); W staged per-k0 in smW[k][n]
__device__ __forceinline__ void mma_gemm_pass(const float* __restrict__ W,
                                              float acc[8][4],
                                              const unsigned* smA, unsigned* smW,
                                              int t, int mt, int nh, int gid, int tig)
{
#pragma unroll
    for (int nt = 0; nt < 8; nt++)
#pragma unroll
        for (int c = 0; c < 4; c++) acc[nt][c] = 0.f;

    int wrow = t >> 1, wq = (t & 1) * 4;
    int r0 = mt * 16 + gid;

    for (int k0 = 0; k0 < FD; k0 += 8) {
        __syncthreads();          // smW reuse from previous slice
        float4 v = *(const float4*)&W[wrow * FD + k0 + wq];
        smW[(wq + 0) * 132 + wrow] = tf32r(v.x);
        smW[(wq + 1) * 132 + wrow] = tf32r(v.y);
        smW[(wq + 2) * 132 + wrow] = tf32r(v.z);
        smW[(wq + 3) * 132 + wrow] = tf32r(v.w);
        __syncthreads();

        unsigned a[4];
        a[0] = smA[r0 * LDA + k0 + tig];
        a[1] = smA[(r0 + 8) * LDA + k0 + tig];
        a[2] = smA[r0 * LDA + k0 + tig + 4];
        a[3] = smA[(r0 + 8) * LDA + k0 + tig + 4];
#pragma unroll
        for (int nt = 0; nt < 8; nt++) {
            int n0 = nh * 64 + nt * 8;
            unsigned b0 = smW[tig * 132 + n0 + gid];
            unsigned b1 = smW[(tig + 4) * 132 + n0 + gid];
            mma_tf32(acc[nt], a, b0, b1);
        }
    }
    __syncthreads();   // everyone done with smA/smW before caller's epilogue
}

__global__ __launch_bounds__(256)
void k_resmlp_mma(const float* __restrict__ x, MlpArgs args, float* __restrict__ out)
{
    __shared__ unsigned smA[64 * LDA];   // 33792 B, tf32 bits
    __shared__ unsigned smW[8 * 132];    // 4224 B, one K slice of W

    int ch = blockIdx.y;
    const float* wr = args.wr[ch];
    const float* brp = args.br[ch];
    const float* w1 = args.w1[ch];
    const float* b1p = args.b1[ch];
    float* dst = (ch == 0) ? out : (ch == 1) ? g_sfea : (ch == 2) ? g_pfea : g_dfea;

    int row0 = blockIdx.x * 64;
    int t = threadIdx.x;
    int w = t >> 5, lane = t & 31;
    int mt = w & 3, nh = w >> 2;
    int gid = lane >> 2, tig = lane & 3;

    // stage silu(x) as tf32
#pragma unroll
    for (int r = 0; r < 8; r++) {
        int e = t + r * 256;
        int m = e >> 5, c4 = e & 31;
        int gr = row0 + m;
        float4 v = make_float4(0.f, 0.f, 0.f, 0.f);
        if (gr < NATOM) v = ((const float4*)x)[gr * 32 + c4];
        smA[m * LDA + c4 * 4 + 0] = tf32r(siluf(v.x));
        smA[m * LDA + c4 * 4 + 1] = tf32r(siluf(v.y));
        smA[m * LDA + c4 * 4 + 2] = tf32r(siluf(v.z));
        smA[m * LDA + c4 * 4 + 3] = tf32r(siluf(v.w));
    }

    float acc[8][4];
    mma_gemm_pass(wr, acc, smA, smW, t, mt, nh, gid, tig);

    // epilogue 1: h = acc + x + br ; smA = tf32(silu(h))
    {
        int r0 = row0 + mt * 16 + gid;
        int r1 = r0 + 8;
#pragma unroll
        for (int nt = 0; nt < 8; nt++) {
            int c = nh * 64 + nt * 8 + 2 * tig;
            float2 br2 = *(const float2*)&brp[c];
            float2 x0 = make_float2(0.f, 0.f), x1 = x0;
            if (r0 < NATOM) x0 = *(const float2*)&x[r0 * FD + c];
            if (r1 < NATOM) x1 = *(const float2*)&x[r1 * FD + c];
            int lr0 = mt * 16 + gid, lr1 = lr0 + 8;
            smA[lr0 * LDA + c]     = tf32r(siluf(acc[nt][0] + x0.x + br2.x));
            smA[lr0 * LDA + c + 1] = tf32r(siluf(acc[nt][1] + x0.y + br2.y));
            smA[lr1 * LDA + c]     = tf32r(siluf(acc[nt][2] + x1.x + br2.x));
            smA[lr1 * LDA + c + 1] = tf32r(siluf(acc[nt][3] + x1.y + br2.y));
        }
    }

    mma_gemm_pass(w1, acc, smA, smW, t, mt, nh, gid, tig);

    // epilogue 2: out = acc + b1
    {
        int r0 = row0 + mt * 16 + gid;
        int r1 = r0 + 8;
#pragma unroll
        for (int nt = 0; nt < 8; nt++) {
            int c = nh * 64 + nt * 8 + 2 * tig;
            float2 b2 = *(const float2*)&b1p[c];
            if (r0 < NATOM)
                *(float2*)&dst[r0 * FD + c] =
                    make_float2(acc[nt][0] + b2.x, acc[nt][1] + b2.y);
            if (r1 < NATOM)
                *(float2*)&dst[r1 * FD + c] =
                    make_float2(acc[nt][2] + b2.x, acc[nt][3] + b2.y);
        }
    }
}

// ---------------- K3: env via tf32 mma ----------------
__global__ __launch_bounds__(128)
void k_env_mma(const int* __restrict__ nbr,
               const float* __restrict__ gs, const float* __restrict__ gp,
               const float* __restrict__ gd,
               const float* __restrict__ Gs, const float* __restrict__ Gp,
               const float* __restrict__ Gd,
               float* __restrict__ out)
{
    __shared__ unsigned sBu[SB_FLOATS];
    __shared__ float sFea[SFEA_FLOATS];

    int t = threadIdx.x;
    int w = t >> 5;
    int lane = t & 31;
    int gid = lane >> 2;
    int tig = lane & 3;

    const float* Gtab[3] = {Gs, Gp, Gd};
    unsigned Afr[3][2][4][4];
#pragma unroll
    for (int ch = 0; ch < 3; ch++) {
        const float* G = Gtab[ch];
#pragma unroll
        for (int mt = 0; mt < 2; mt++) {
#pragma unroll
            for (int k4 = 0; k4 < 4; k4++) {
                int r0 = w * 32 + mt * 16 + gid;
                int c0 = k4 * 8 + tig;
                Afr[ch][mt][k4][0] = tf32r(G[r0 * 32 + c0]);
                Afr[ch][mt][k4][1] = tf32r(G[(r0 + 8) * 32 + c0]);
                Afr[ch][mt][k4][2] = tf32r(G[r0 * 32 + c0 + 4]);
                Afr[ch][mt][k4][3] = tf32r(G[(r0 + 8) * 32 + c0 + 4]);
            }
        }
    }

    const float4* gs4 = (const float4*)gs;
    const float4* gp4 = (const float4*)gp;
    const float4* gd4 = (const float4*)gd;

    for (int n = blockIdx.x; n < NATOM; n += gridDim.x) {
        int jn[NNJ];
#pragma unroll
        for (int j = 0; j < NNJ; j++) jn[j] = nbr[n * NNJ + j];

#pragma unroll
        for (int r = 0; r < 9; r++) {
            int e = t + r * 128;
            int k = e / 36, pc = e % 36;
            int g = pc >> 2, jj = pc & 3;
            sBu[k * LDB + g * 16 + 12 + jj] = 0u;
        }
        if (t < 96) {
            float4 v = gs4[(size_t)n * 96 + t];
            int j = t >> 3, q = t & 7;
            int base = (q * 4) * LDB + j;
            sBu[base]            = tf32r(v.x);
            sBu[base + LDB]      = tf32r(v.y);
            sBu[base + 2 * LDB]  = tf32r(v.z);
            sBu[base + 3 * LDB]  = tf32r(v.w);
        }
#pragma unroll
        for (int r = 0; r < 3; r++) {
            int e = t + r * 128;
            if (e < 288) {
                float4 v = gp4[(size_t)n * 288 + e];
                float vv[4] = {v.x, v.y, v.z, v.w};
#pragma unroll
                for (int u = 0; u < 4; u++) {
                    int idx = e * 4 + u;
                    int j = idx / 96, rr = idx % 96;
                    int k = rr / 3, a = rr % 3;
                    sBu[k * LDB + 16 + a * 16 + j] = tf32r(vv[u]);
                }
            }
        }
#pragma unroll
        for (int r = 0; r < 4; r++) {
            int e = t + r * 128;
            if (e < 480) {
                float4 v = gd4[(size_t)n * 480 + e];
                float vv[4] = {v.x, v.y, v.z, v.w};
#pragma unroll
                for (int u = 0; u < 4; u++) {
                    int idx = e * 4 + u;
                    int j = idx / 160, rr = idx % 160;
                    int k = rr / 5, a = rr % 5;
                    sBu[k * LDB + 64 + a * 16 + j] = tf32r(vv[u]);
                }
            }
        }
        {
            const float* feaP[3] = {g_sfea, g_pfea, g_dfea};
#pragma unroll
            for (int ch = 0; ch < 3; ch++) {
                float* row = sFea + ch * (128 * FEA_LD) + t * FEA_LD;
#pragma unroll
                for (int j = 0; j < NNJ; j++)
                    row[j] = feaP[ch][(size_t)jn[j] * FD + t];
#pragma unroll
                for (int j = NNJ; j < 16; j++) row[j] = 0.f;
            }
        }

        __syncthreads();

        float P[2][2][9];
#pragma unroll
        for (int mt = 0; mt < 2; mt++)
#pragma unroll
            for (int rr = 0; rr < 2; rr++)
#pragma unroll
                for (int q = 0; q < 9; q++) P[mt][rr][q] = 0.f;

#pragma unroll
        for (int ch = 0; ch < 3; ch++) {
            const int NA = (ch == 0) ? 1 : (ch == 1) ? 3 : 5;
            const int CB = (ch == 0) ? 0 : (ch == 1) ? 16 : 64;
            const int PB = (ch == 0) ? 0 : (ch == 1) ? 1 : 4;
#pragma unroll
            for (int a = 0; a < NA; a++) {
#pragma unroll
                for (int half = 0; half < 2; half++) {
                    int cb = CB + a * 16 + half * 8;
                    unsigned bf[8];
#pragma unroll
                    for (int k4 = 0; k4 < 4; k4++) {
                        bf[2 * k4]     = sBu[(k4 * 8 + tig) * LDB + cb + gid];
                        bf[2 * k4 + 1] = sBu[(k4 * 8 + tig + 4) * LDB + cb + gid];
                    }
                    int j0 = half * 8 + 2 * tig;
#pragma unroll
                    for (int mt = 0; mt < 2; mt++) {
                        float C[4] = {0.f, 0.f, 0.f, 0.f};
#pragma unroll
                        for (int k4 = 0; k4 < 4; k4++)
                            mma_tf32(C, Afr[ch][mt][k4], bf[2 * k4], bf[2 * k4 + 1]);
                        int r = w * 32 + mt * 16 + gid;
                        const float* fr0 = sFea + ch * (128 * FEA_LD) + r * FEA_LD;
                        const float* fr1 = fr0 + 8 * FEA_LD;
                        P[mt][0][PB + a] += C[0] * fr0[j0] + C[1] * fr0[j0 + 1];
                        P[mt][1][PB + a] += C[2] * fr1[j0] + C[3] * fr1[j0 + 1];
                    }
                }
            }
        }

#pragma unroll
        for (int mt = 0; mt < 2; mt++) {
#pragma unroll
            for (int rr = 0; rr < 2; rr++) {
#pragma unroll
                for (int q = 0; q < 9; q++) {
                    float v = P[mt][rr][q];
                    v += __shfl_xor_sync(0xffffffffu, v, 1);
                    v += __shfl_xor_sync(0xffffffffu, v, 2);
                    if (tig == 0) {
                        int r = w * 32 + mt * 16 + rr * 8 + gid;
                        if (q == 0)
                            out[(size_t)n * FD + r] += v;
                        else if (q < 4)
                            g_allp[((size_t)n * 3 + (q - 1)) * FD + r] = v;
                        else
                            g_alld[((size_t)n * 5 + (q - 4)) * FD + r] = v;
                    }
                }
            }
        }

        __syncthreads();
    }
}

// ---------------- K4: rowdot[r] = v_r . (M v_r) via tf32 mma ----------------
__global__ __launch_bounds__(256)
void k_quad_mma(int which)
{
    const float* V = which ? g_alld : g_allp;
    const float* M = which ? g_Md : g_Mp;
    float* rowdot = which ? g_rowd : g_rowp;
    int R = which ? NATOM * 5 : NATOM * 3;

    __shared__ unsigned smA[64 * LDA];   // tf32 bits of V tile
    __shared__ float sPart[2][4][16];

    int row0 = blockIdx.x * 64;
    int t = threadIdx.x;
    int w = t >> 5, lane = t & 31;
    int mt = w & 3, nh = w >> 2;
    int gid = lane >> 2, tig = lane & 3;

    // stage V tile as tf32
#pragma unroll
    for (int r = 0; r < 8; r++) {
        int e = t + r * 256;
        int m = e >> 5, c4 = e & 31;
        int gr = row0 + m;
        float4 v = make_float4(0.f, 0.f, 0.f, 0.f);
        if (gr < R) v = ((const float4*)V)[gr * 32 + c4];
        smA[m * LDA + c4 * 4 + 0] = tf32r(v.x);
        smA[m * LDA + c4 * 4 + 1] = tf32r(v.y);
        smA[m * LDA + c4 * 4 + 2] = tf32r(v.z);
        smA[m * LDA + c4 * 4 + 3] = tf32r(v.w);
    }
    __syncthreads();

    float acc[8][4];
#pragma unroll
    for (int nt = 0; nt < 8; nt++)
#pragma unroll
        for (int c = 0; c < 4; c++) acc[nt][c] = 0.f;

    for (int k0 = 0; k0 < FD; k0 += 8) {
        unsigned a[4];
        int r0 = mt * 16 + gid;
        a[0] = smA[r0 * LDA + k0 + tig];
        a[1] = smA[(r0 + 8) * LDA + k0 + tig];
        a[2] = smA[r0 * LDA + k0 + tig + 4];
        a[3] = smA[(r0 + 8) * LDA + k0 + tig + 4];
#pragma unroll
        for (int nt = 0; nt < 8; nt++) {
            int n0 = nh * 64 + nt * 8;
            // B element (k=f, n=g) = M[f][g]
            unsigned b0 = tf32r(M[(k0 + tig) * FD + n0 + gid]);
            unsigned b1 = tf32r(M[(k0 + tig + 4) * FD + n0 + gid]);
            mma_tf32(acc[nt], a, b0, b1);
        }
    }

    // fused row dot vs smem V (tf32-truncated)
    float d0 = 0.f, d1 = 0.f;
    {
        int lr0 = mt * 16 + gid, lr1 = lr0 + 8;
#pragma unroll
        for (int nt = 0; nt < 8; nt++) {
            int c = nh * 64 + nt * 8 + 2 * tig;
            float v00 = __uint_as_float(smA[lr0 * LDA + c]);
            float v01 = __uint_as_float(smA[lr0 * LDA + c + 1]);
            float v10 = __uint_as_float(smA[lr1 * LDA + c]);
            float v11 = __uint_as_float(smA[lr1 * LDA + c + 1]);
            d0 = fmaf(acc[nt][0], v00, fmaf(acc[nt][1], v01, d0));
            d1 = fmaf(acc[nt][2], v10, fmaf(acc[nt][3], v11, d1));
        }
    }
    d0 += __shfl_xor_sync(0xffffffffu, d0, 1);
    d0 += __shfl_xor_sync(0xffffffffu, d0, 2);
    d1 += __shfl_xor_sync(0xffffffffu, d1, 1);
    d1 += __shfl_xor_sync(0xffffffffu, d1, 2);
    if (tig == 0) {
        sPart[nh][mt][gid] = d0;
        sPart[nh][mt][gid + 8] = d1;
    }
    __syncthreads();

    if (t < 64) {
        int mtt = t >> 4, r = t & 15;
        int gr = row0 + mtt * 16 + r;
        if (gr < R) rowdot[gr] = sPart[0][mtt][r] + sPart[1][mtt][r];
    }
}

// ---------------- K5: broadcast scalar add (float4) ----------------
__global__ void k_final(float* __restrict__ out)
{
    int idx4 = blockIdx.x * blockDim.x + threadIdx.x;
    if (idx4 >= NATOM * FD / 4) return;
    int n = idx4 >> 5;
    float s = g_rowp[n * 3 + 0] + g_rowp[n * 3 + 1] + g_rowp[n * 3 + 2]
            + g_rowd[n * 5 + 0] + g_rowd[n * 5 + 1] + g_rowd[n * 5 + 2]
            + g_rowd[n * 5 + 3] + g_rowd[n * 5 + 4];
    float4 o = ((float4*)out)[idx4];
    o.x += s; o.y += s; o.z += s; o.w += s;
    ((float4*)out)[idx4] = o;
}

// ---------------- launch ----------------
extern "C" void kernel_launch(void* const* d_in, const int* in_sizes, int n_in,
                              void* d_out, int out_size)
{
    const float* atom = (const float*)d_in[0];
    const int*   nbr  = (const int*)d_in[1];
    const float* gs   = (const float*)d_in[2];
    const float* gp   = (const float*)d_in[3];
    const float* gd   = (const float*)d_in[4];
    const float* Gs   = (const float*)d_in[5];
    const float* Gp   = (const float*)d_in[6];
    const float* Gd   = (const float*)d_in[7];
    const float* P1   = (const float*)d_in[8];
    const float* P2   = (const float*)d_in[9];
    const float* D1   = (const float*)d_in[10];
    const float* D2   = (const float*)d_in[11];
    float* out = (float*)d_out;

    MlpArgs a;
    for (int ch = 0; ch < 4; ch++) {
        a.wr[ch] = (const float*)d_in[12 + ch * 4 + 0];
        a.br[ch] = (const float*)d_in[12 + ch * 4 + 1];
        a.w1[ch] = (const float*)d_in[12 + ch * 4 + 2];
        a.b1[ch] = (const float*)d_in[12 + ch * 4 + 3];
    }

    k_mmt<<<dim3(16, 2), 128>>>(P1, P2, D1, D2);
    k_resmlp_mma<<<dim3((NATOM + 63) / 64, 4), 256>>>(atom, a, out);
    k_env_mma<<<740, 128>>>(nbr, gs, gp, gd, Gs, Gp, Gd, out);
    k_quad_mma<<<(NATOM * 3 + 63) / 64, 256>>>(0);
    k_quad_mma<<<(NATOM * 5 + 63) / 64, 256>>>(1);
    k_final<<<(NATOM * FD / 4 + 255) / 256, 256>>>(out);
}

// round 11
// speedup vs baseline: 1.8297x; 1.0288x over previous
#include <cuda_runtime.h>

#define NATOM 30000
#define NNJ 12
#define KD 32
#define FD 128
#define LDA 132

// sB layout: [32 k][152 cols]; cols: s [0,16), p a*16+[16,64), d a*16+[64,144), pads zeroed
#define LDB 152
#define SB_FLOATS (32 * LDB)           // 4864
#define FEA_LD 17
#define SFEA_FLOATS (3 * 128 * FEA_LD) // 6528

#define NP_BLK 1407   // ceil(30000*3/64)
#define ND_BLK 2344   // ceil(30000*5/64)

// ---------------- device scratch ----------------
__device__ float g_sfea[NATOM * FD];
__device__ float g_pfea[NATOM * FD];
__device__ float g_dfea[NATOM * FD];
__device__ float g_allp[NATOM * 3 * FD];   // [n][a][f]
__device__ float g_alld[NATOM * 5 * FD];   // [n][a][f]
__device__ float g_Mp[FD * FD];            // P1 @ P2^T
__device__ float g_Md[FD * FD];            // D1 @ D2^T
__device__ float g_rowp[NATOM * 3];
__device__ float g_rowd[NATOM * 5];

__device__ __forceinline__ float siluf(float x) {
    return x / (1.0f + __expf(-x));
}

__device__ __forceinline__ unsigned tf32r(float x) {
    unsigned u;
    asm("cvt.rna.tf32.f32 %0, %1;" : "=r"(u) : "f"(x));
    return u;
}

__device__ __forceinline__ void mma_tf32(float c[4], const unsigned a[4],
                                         unsigned b0, unsigned b1) {
    asm volatile(
        "mma.sync.aligned.m16n8k8.row.col.f32.tf32.tf32.f32 "
        "{%0,%1,%2,%3},{%4,%5,%6,%7},{%8,%9},{%0,%1,%2,%3};"
        : "+f"(c[0]), "+f"(c[1]), "+f"(c[2]), "+f"(c[3])
        : "r"(a[0]), "r"(a[1]), "r"(a[2]), "r"(a[3]), "r"(b0), "r"(b1));
}

// ---------------- K1: Mp = P1 @ P2^T, Md = D1 @ D2^T ----------------
__global__ __launch_bounds__(128)
void k_mmt(const float* __restrict__ P1, const float* __restrict__ P2,
           const float* __restrict__ D1, const float* __restrict__ D2)
{
    const float* A = blockIdx.y ? D1 : P1;
    const float* B = blockIdx.y ? D2 : P2;
    float* M = blockIdx.y ? g_Md : g_Mp;

    __shared__ float smA[8 * FD];
    __shared__ float smB[16 * LDA];
    int t = threadIdx.x;
    int i0 = blockIdx.x * 8;

#pragma unroll
    for (int r = 0; r < 2; r++) {
        int e = t + r * 128;
        ((float4*)smA)[e] = ((const float4*)A)[i0 * 32 + e];
    }

    float acc[8];
#pragma unroll
    for (int i = 0; i < 8; i++) acc[i] = 0.f;

    for (int g0 = 0; g0 < FD; g0 += 16) {
        __syncthreads();
#pragma unroll
        for (int r = 0; r < 4; r++) {
            int e = t + r * 128;
            int j = e >> 2, q = e & 3;
            float4 v = ((const float4*)B)[j * 32 + (g0 >> 2) + q];
            smB[(q * 4 + 0) * LDA + j] = v.x;
            smB[(q * 4 + 1) * LDA + j] = v.y;
            smB[(q * 4 + 2) * LDA + j] = v.z;
            smB[(q * 4 + 3) * LDA + j] = v.w;
        }
        __syncthreads();
#pragma unroll
        for (int gl = 0; gl < 16; gl++) {
            float b = smB[gl * LDA + t];
#pragma unroll
            for (int i = 0; i < 8; i++)
                acc[i] = fmaf(smA[i * FD + g0 + gl], b, acc[i]);
        }
    }
#pragma unroll
    for (int i = 0; i < 8; i++) M[(i0 + i) * FD + t] = acc[i];
}

// ---------------- K2: fused ResMLP via tf32 mma, smem-staged W (16-wide) ----------------
struct MlpArgs {
    const float* wr[4]; const float* br[4];
    const float* w1[4]; const float* b1[4];
};

__device__ __forceinline__ void mma_gemm_pass(const float* __restrict__ W,
                                              float acc[8][4],
                                              const unsigned* smA, unsigned* smW,
                                              int t, int mt, int nh, int gid, int tig)
{
#pragma unroll
    for (int nt = 0; nt < 8; nt++)
#pragma unroll
        for (int c = 0; c < 4; c++) acc[nt][c] = 0.f;

    int wrow = t >> 1, wq = (t & 1) * 8;
    int r0 = mt * 16 + gid;

    for (int k0 = 0; k0 < FD; k0 += 16) {
        __syncthreads();          // smW reuse from previous slice
        float4 v0 = *(const float4*)&W[wrow * FD + k0 + wq];
        float4 v1 = *(const float4*)&W[wrow * FD + k0 + wq + 4];
        smW[(wq + 0) * 132 + wrow] = tf32r(v0.x);
        smW[(wq + 1) * 132 + wrow] = tf32r(v0.y);
        smW[(wq + 2) * 132 + wrow] = tf32r(v0.z);
        smW[(wq + 3) * 132 + wrow] = tf32r(v0.w);
        smW[(wq + 4) * 132 + wrow] = tf32r(v1.x);
        smW[(wq + 5) * 132 + wrow] = tf32r(v1.y);
        smW[(wq + 6) * 132 + wrow] = tf32r(v1.z);
        smW[(wq + 7) * 132 + wrow] = tf32r(v1.w);
        __syncthreads();

#pragma unroll
        for (int kk = 0; kk < 16; kk += 8) {
            unsigned a[4];
            a[0] = smA[r0 * LDA + k0 + kk + tig];
            a[1] = smA[(r0 + 8) * LDA + k0 + kk + tig];
            a[2] = smA[r0 * LDA + k0 + kk + tig + 4];
            a[3] = smA[(r0 + 8) * LDA + k0 + kk + tig + 4];
#pragma unroll
            for (int nt = 0; nt < 8; nt++) {
                int n0 = nh * 64 + nt * 8;
                unsigned b0 = smW[(kk + tig) * 132 + n0 + gid];
                unsigned b1 = smW[(kk + tig + 4) * 132 + n0 + gid];
                mma_tf32(acc[nt], a, b0, b1);
            }
        }
    }
    __syncthreads();
}

__global__ __launch_bounds__(256)
void k_resmlp_mma(const float* __restrict__ x, MlpArgs args, float* __restrict__ out)
{
    __shared__ unsigned smA[64 * LDA];
    __shared__ unsigned smW[16 * 132];

    int ch = blockIdx.y;
    const float* wr = args.wr[ch];
    const float* brp = args.br[ch];
    const float* w1 = args.w1[ch];
    const float* b1p = args.b1[ch];
    float* dst = (ch == 0) ? out : (ch == 1) ? g_sfea : (ch == 2) ? g_pfea : g_dfea;

    int row0 = blockIdx.x * 64;
    int t = threadIdx.x;
    int w = t >> 5, lane = t & 31;
    int mt = w & 3, nh = w >> 2;
    int gid = lane >> 2, tig = lane & 3;

#pragma unroll
    for (int r = 0; r < 8; r++) {
        int e = t + r * 256;
        int m = e >> 5, c4 = e & 31;
        int gr = row0 + m;
        float4 v = make_float4(0.f, 0.f, 0.f, 0.f);
        if (gr < NATOM) v = ((const float4*)x)[gr * 32 + c4];
        smA[m * LDA + c4 * 4 + 0] = tf32r(siluf(v.x));
        smA[m * LDA + c4 * 4 + 1] = tf32r(siluf(v.y));
        smA[m * LDA + c4 * 4 + 2] = tf32r(siluf(v.z));
        smA[m * LDA + c4 * 4 + 3] = tf32r(siluf(v.w));
    }

    float acc[8][4];
    mma_gemm_pass(wr, acc, smA, smW, t, mt, nh, gid, tig);

    {
        int r0 = row0 + mt * 16 + gid;
        int r1 = r0 + 8;
#pragma unroll
        for (int nt = 0; nt < 8; nt++) {
            int c = nh * 64 + nt * 8 + 2 * tig;
            float2 br2 = *(const float2*)&brp[c];
            float2 x0 = make_float2(0.f, 0.f), x1 = x0;
            if (r0 < NATOM) x0 = *(const float2*)&x[r0 * FD + c];
            if (r1 < NATOM) x1 = *(const float2*)&x[r1 * FD + c];
            int lr0 = mt * 16 + gid, lr1 = lr0 + 8;
            smA[lr0 * LDA + c]     = tf32r(siluf(acc[nt][0] + x0.x + br2.x));
            smA[lr0 * LDA + c + 1] = tf32r(siluf(acc[nt][1] + x0.y + br2.y));
            smA[lr1 * LDA + c]     = tf32r(siluf(acc[nt][2] + x1.x + br2.x));
            smA[lr1 * LDA + c + 1] = tf32r(siluf(acc[nt][3] + x1.y + br2.y));
        }
    }

    mma_gemm_pass(w1, acc, smA, smW, t, mt, nh, gid, tig);

    {
        int r0 = row0 + mt * 16 + gid;
        int r1 = r0 + 8;
#pragma unroll
        for (int nt = 0; nt < 8; nt++) {
            int c = nh * 64 + nt * 8 + 2 * tig;
            float2 b2 = *(const float2*)&b1p[c];
            if (r0 < NATOM)
                *(float2*)&dst[r0 * FD + c] =
                    make_float2(acc[nt][0] + b2.x, acc[nt][1] + b2.y);
            if (r1 < NATOM)
                *(float2*)&dst[r1 * FD + c] =
                    make_float2(acc[nt][2] + b2.x, acc[nt][3] + b2.y);
        }
    }
}

// ---------------- K3: env via tf32 mma (R7-passing version, grid 740) ----------------
__global__ __launch_bounds__(128)
void k_env_mma(const int* __restrict__ nbr,
               const float* __restrict__ gs, const float* __restrict__ gp,
               const float* __restrict__ gd,
               const float* __restrict__ Gs, const float* __restrict__ Gp,
               const float* __restrict__ Gd,
               float* __restrict__ out)
{
    __shared__ unsigned sBu[SB_FLOATS];
    __shared__ float sFea[SFEA_FLOATS];

    int t = threadIdx.x;
    int w = t >> 5;
    int lane = t & 31;
    int gid = lane >> 2;
    int tig = lane & 3;

    const float* Gtab[3] = {Gs, Gp, Gd};
    unsigned Afr[3][2][4][4];
#pragma unroll
    for (int ch = 0; ch < 3; ch++) {
        const float* G = Gtab[ch];
#pragma unroll
        for (int mt = 0; mt < 2; mt++) {
#pragma unroll
            for (int k4 = 0; k4 < 4; k4++) {
                int r0 = w * 32 + mt * 16 + gid;
                int c0 = k4 * 8 + tig;
                Afr[ch][mt][k4][0] = tf32r(G[r0 * 32 + c0]);
                Afr[ch][mt][k4][1] = tf32r(G[(r0 + 8) * 32 + c0]);
                Afr[ch][mt][k4][2] = tf32r(G[r0 * 32 + c0 + 4]);
                Afr[ch][mt][k4][3] = tf32r(G[(r0 + 8) * 32 + c0 + 4]);
            }
        }
    }

    const float4* gs4 = (const float4*)gs;
    const float4* gp4 = (const float4*)gp;
    const float4* gd4 = (const float4*)gd;

    for (int n = blockIdx.x; n < NATOM; n += gridDim.x) {
        int jn[NNJ];
#pragma unroll
        for (int j = 0; j < NNJ; j++) jn[j] = nbr[n * NNJ + j];

#pragma unroll
        for (int r = 0; r < 9; r++) {
            int e = t + r * 128;
            int k = e / 36, pc = e % 36;
            int g = pc >> 2, jj = pc & 3;
            sBu[k * LDB + g * 16 + 12 + jj] = 0u;
        }
        if (t < 96) {
            float4 v = gs4[(size_t)n * 96 + t];
            int j = t >> 3, q = t & 7;
            int base = (q * 4) * LDB + j;
            sBu[base]            = tf32r(v.x);
            sBu[base + LDB]      = tf32r(v.y);
            sBu[base + 2 * LDB]  = tf32r(v.z);
            sBu[base + 3 * LDB]  = tf32r(v.w);
        }
#pragma unroll
        for (int r = 0; r < 3; r++) {
            int e = t + r * 128;
            if (e < 288) {
                float4 v = gp4[(size_t)n * 288 + e];
                float vv[4] = {v.x, v.y, v.z, v.w};
#pragma unroll
                for (int u = 0; u < 4; u++) {
                    int idx = e * 4 + u;
                    int j = idx / 96, rr = idx % 96;
                    int k = rr / 3, a = rr % 3;
                    sBu[k * LDB + 16 + a * 16 + j] = tf32r(vv[u]);
                }
            }
        }
#pragma unroll
        for (int r = 0; r < 4; r++) {
            int e = t + r * 128;
            if (e < 480) {
                float4 v = gd4[(size_t)n * 480 + e];
                float vv[4] = {v.x, v.y, v.z, v.w};
#pragma unroll
                for (int u = 0; u < 4; u++) {
                    int idx = e * 4 + u;
                    int j = idx / 160, rr = idx % 160;
                    int k = rr / 5, a = rr % 5;
                    sBu[k * LDB + 64 + a * 16 + j] = tf32r(vv[u]);
                }
            }
        }
        {
            const float* feaP[3] = {g_sfea, g_pfea, g_dfea};
#pragma unroll
            for (int ch = 0; ch < 3; ch++) {
                float* row = sFea + ch * (128 * FEA_LD) + t * FEA_LD;
#pragma unroll
                for (int j = 0; j < NNJ; j++)
                    row[j] = feaP[ch][(size_t)jn[j] * FD + t];
#pragma unroll
                for (int j = NNJ; j < 16; j++) row[j] = 0.f;
            }
        }

        __syncthreads();

        float P[2][2][9];
#pragma unroll
        for (int mt = 0; mt < 2; mt++)
#pragma unroll
            for (int rr = 0; rr < 2; rr++)
#pragma unroll
                for (int q = 0; q < 9; q++) P[mt][rr][q] = 0.f;

#pragma unroll
        for (int ch = 0; ch < 3; ch++) {
            const int NA = (ch == 0) ? 1 : (ch == 1) ? 3 : 5;
            const int CB = (ch == 0) ? 0 : (ch == 1) ? 16 : 64;
            const int PB = (ch == 0) ? 0 : (ch == 1) ? 1 : 4;
#pragma unroll
            for (int a = 0; a < NA; a++) {
#pragma unroll
                for (int half = 0; half < 2; half++) {
                    int cb = CB + a * 16 + half * 8;
                    unsigned bf[8];
#pragma unroll
                    for (int k4 = 0; k4 < 4; k4++) {
                        bf[2 * k4]     = sBu[(k4 * 8 + tig) * LDB + cb + gid];
                        bf[2 * k4 + 1] = sBu[(k4 * 8 + tig + 4) * LDB + cb + gid];
                    }
                    int j0 = half * 8 + 2 * tig;
#pragma unroll
                    for (int mt = 0; mt < 2; mt++) {
                        float C[4] = {0.f, 0.f, 0.f, 0.f};
#pragma unroll
                        for (int k4 = 0; k4 < 4; k4++)
                            mma_tf32(C, Afr[ch][mt][k4], bf[2 * k4], bf[2 * k4 + 1]);
                        int r = w * 32 + mt * 16 + gid;
                        const float* fr0 = sFea + ch * (128 * FEA_LD) + r * FEA_LD;
                        const float* fr1 = fr0 + 8 * FEA_LD;
                        P[mt][0][PB + a] += C[0] * fr0[j0] + C[1] * fr0[j0 + 1];
                        P[mt][1][PB + a] += C[2] * fr1[j0] + C[3] * fr1[j0 + 1];
                    }
                }
            }
        }

#pragma unroll
        for (int mt = 0; mt < 2; mt++) {
#pragma unroll
            for (int rr = 0; rr < 2; rr++) {
#pragma unroll
                for (int q = 0; q < 9; q++) {
                    float v = P[mt][rr][q];
                    v += __shfl_xor_sync(0xffffffffu, v, 1);
                    v += __shfl_xor_sync(0xffffffffu, v, 2);
                    if (tig == 0) {
                        int r = w * 32 + mt * 16 + rr * 8 + gid;
                        if (q == 0)
                            out[(size_t)n * FD + r] += v;
                        else if (q < 4)
                            g_allp[((size_t)n * 3 + (q - 1)) * FD + r] = v;
                        else
                            g_alld[((size_t)n * 5 + (q - 4)) * FD + r] = v;
                    }
                }
            }
        }

        __syncthreads();
    }
}

// ---------------- K4: rowdot[r] = v_r . (M v_r), merged p+d, smem-staged M ----------------
__global__ __launch_bounds__(256)
void k_quad_mma()
{
    int bid = blockIdx.x;
    int which = (bid >= NP_BLK) ? 1 : 0;
    const float* V = which ? g_alld : g_allp;
    const float* M = which ? g_Md : g_Mp;
    float* rowdot = which ? g_rowd : g_rowp;
    int R = which ? NATOM * 5 : NATOM * 3;
    int row0 = (which ? bid - NP_BLK : bid) * 64;

    __shared__ unsigned smA[64 * LDA];
    __shared__ unsigned smW[16 * 132];
    __shared__ float sPart[2][4][16];

    int t = threadIdx.x;
    int w = t >> 5, lane = t & 31;
    int mt = w & 3, nh = w >> 2;
    int gid = lane >> 2, tig = lane & 3;

#pragma unroll
    for (int r = 0; r < 8; r++) {
        int e = t + r * 256;
        int m = e >> 5, c4 = e & 31;
        int gr = row0 + m;
        float4 v = make_float4(0.f, 0.f, 0.f, 0.f);
        if (gr < R) v = ((const float4*)V)[gr * 32 + c4];
        smA[m * LDA + c4 * 4 + 0] = tf32r(v.x);
        smA[m * LDA + c4 * 4 + 1] = tf32r(v.y);
        smA[m * LDA + c4 * 4 + 2] = tf32r(v.z);
        smA[m * LDA + c4 * 4 + 3] = tf32r(v.w);
    }

    float acc[8][4];
#pragma unroll
    for (int nt = 0; nt < 8; nt++)
#pragma unroll
        for (int c = 0; c < 4; c++) acc[nt][c] = 0.f;

    int kr = t >> 4, c8 = (t & 15) * 8;
    int r0 = mt * 16 + gid;

    for (int k0 = 0; k0 < FD; k0 += 16) {
        __syncthreads();
        float4 v0 = *(const float4*)&M[(k0 + kr) * FD + c8];
        float4 v1 = *(const float4*)&M[(k0 + kr) * FD + c8 + 4];
        smW[kr * 132 + c8 + 0] = tf32r(v0.x);
        smW[kr * 132 + c8 + 1] = tf32r(v0.y);
        smW[kr * 132 + c8 + 2] = tf32r(v0.z);
        smW[kr * 132 + c8 + 3] = tf32r(v0.w);
        smW[kr * 132 + c8 + 4] = tf32r(v1.x);
        smW[kr * 132 + c8 + 5] = tf32r(v1.y);
        smW[kr * 132 + c8 + 6] = tf32r(v1.z);
        smW[kr * 132 + c8 + 7] = tf32r(v1.w);
        __syncthreads();

#pragma unroll
        for (int kk = 0; kk < 16; kk += 8) {
            unsigned a[4];
            a[0] = smA[r0 * LDA + k0 + kk + tig];
            a[1] = smA[(r0 + 8) * LDA + k0 + kk + tig];
            a[2] = smA[r0 * LDA + k0 + kk + tig + 4];
            a[3] = smA[(r0 + 8) * LDA + k0 + kk + tig + 4];
#pragma unroll
            for (int nt = 0; nt < 8; nt++) {
                int n0 = nh * 64 + nt * 8;
                unsigned b0 = smW[(kk + tig) * 132 + n0 + gid];
                unsigned b1 = smW[(kk + tig + 4) * 132 + n0 + gid];
                mma_tf32(acc[nt], a, b0, b1);
            }
        }
    }

    // fused row dot vs smem V (tf32-truncated)
    float d0 = 0.f, d1 = 0.f;
    {
        int lr0 = mt * 16 + gid, lr1 = lr0 + 8;
#pragma unroll
        for (int nt = 0; nt < 8; nt++) {
            int c = nh * 64 + nt * 8 + 2 * tig;
            float v00 = __uint_as_float(smA[lr0 * LDA + c]);
            float v01 = __uint_as_float(smA[lr0 * LDA + c + 1]);
            float v10 = __uint_as_float(smA[lr1 * LDA + c]);
            float v11 = __uint_as_float(smA[lr1 * LDA + c + 1]);
            d0 = fmaf(acc[nt][0], v00, fmaf(acc[nt][1], v01, d0));
            d1 = fmaf(acc[nt][2], v10, fmaf(acc[nt][3], v11, d1));
        }
    }
    d0 += __shfl_xor_sync(0xffffffffu, d0, 1);
    d0 += __shfl_xor_sync(0xffffffffu, d0, 2);
    d1 += __shfl_xor_sync(0xffffffffu, d1, 1);
    d1 += __shfl_xor_sync(0xffffffffu, d1, 2);
    if (tig == 0) {
        sPart[nh][mt][gid] = d0;
        sPart[nh][mt][gid + 8] = d1;
    }
    __syncthreads();

    if (t < 64) {
        int mtt = t >> 4, r = t & 15;
        int gr = row0 + mtt * 16 + r;
        if (gr < R) rowdot[gr] = sPart[0][mtt][r] + sPart[1][mtt][r];
    }
}

// ---------------- K5: broadcast scalar add (float4) ----------------
__global__ void k_final(float* __restrict__ out)
{
    int idx4 = blockIdx.x * blockDim.x + threadIdx.x;
    if (idx4 >= NATOM * FD / 4) return;
    int n = idx4 >> 5;
    float s = g_rowp[n * 3 + 0] + g_rowp[n * 3 + 1] + g_rowp[n * 3 + 2]
            + g_rowd[n * 5 + 0] + g_rowd[n * 5 + 1] + g_rowd[n * 5 + 2]
            + g_rowd[n * 5 + 3] + g_rowd[n * 5 + 4];
    float4 o = ((float4*)out)[idx4];
    o.x += s; o.y += s; o.z += s; o.w += s;
    ((float4*)out)[idx4] = o;
}

// ---------------- launch ----------------
extern "C" void kernel_launch(void* const* d_in, const int* in_sizes, int n_in,
                              void* d_out, int out_size)
{
    const float* atom = (const float*)d_in[0];
    const int*   nbr  = (const int*)d_in[1];
    const float* gs   = (const float*)d_in[2];
    const float* gp   = (const float*)d_in[3];
    const float* gd   = (const float*)d_in[4];
    const float* Gs   = (const float*)d_in[5];
    const float* Gp   = (const float*)d_in[6];
    const float* Gd   = (const float*)d_in[7];
    const float* P1   = (const float*)d_in[8];
    const float* P2   = (const float*)d_in[9];
    const float* D1   = (const float*)d_in[10];
    const float* D2   = (const float*)d_in[11];
    float* out = (float*)d_out;

    MlpArgs a;
    for (int ch = 0; ch < 4; ch++) {
        a.wr[ch] = (const float*)d_in[12 + ch * 4 + 0];
        a.br[ch] = (const float*)d_in[12 + ch * 4 + 1];
        a.w1[ch] = (const float*)d_in[12 + ch * 4 + 2];
        a.b1[ch] = (const float*)d_in[12 + ch * 4 + 3];
    }

    k_mmt<<<dim3(16, 2), 128>>>(P1, P2, D1, D2);
    k_resmlp_mma<<<dim3((NATOM + 63) / 64, 4), 256>>>(atom, a, out);
    k_env_mma<<<740, 128>>>(nbr, gs, gp, gd, Gs, Gp, Gd, out);
    k_quad_mma<<<NP_BLK + ND_BLK, 256>>>();
    k_final<<<(NATOM * FD / 4 + 255) / 256, 256>>>(out);
}